// round 4
// baseline (speedup 1.0000x reference)
#include <cuda_runtime.h>
#include <cuda_bf16.h>
#include <math.h>

#define Bb 4
#define TQn 2048
#define Tn 2048
#define En 2048
#define Hn 16
#define Dn 128
#define HDn 2048
#define NTOK 8192
#define POSN 4096
#define KVS 132
#define SSD 68

__device__ float g_Q[(size_t)NTOK * HDn];
__device__ float g_K[(size_t)NTOK * HDn];
__device__ float g_V[(size_t)NTOK * HDn];
__device__ float g_Y[(size_t)NTOK * HDn];
__device__ float g_cos[POSN * 64];
__device__ float g_sin[POSN * 64];
__device__ float g_maskf[Bb * Tn];
__device__ int   g_kind;

__device__ __forceinline__ float2 ffma2(float2 a, float2 b, float2 c) {
    unsigned long long ua, ub, uc;
    __builtin_memcpy(&ua, &a, 8);
    __builtin_memcpy(&ub, &b, 8);
    __builtin_memcpy(&uc, &c, 8);
    asm("fma.rn.f32x2 %0, %1, %2, %0;" : "+l"(uc) : "l"(ua), "l"(ub));
    float2 r; __builtin_memcpy(&r, &uc, 8);
    return r;
}

__device__ __forceinline__ float neginf() { return __int_as_float(0xff800000u); }

// ---------------- RoPE tables (fp64 -> f32, mimics reference's f32 table) ----
__global__ void ropetab_kernel() {
    int t = blockIdx.x * 256 + threadIdx.x;
    if (t >= POSN * 64) return;
    int j = t & 63, p = t >> 6;
    double inv = 1.0 / pow(10000.0, (double)(2 * j) / 128.0);
    float invf = (float)inv;
    float ang = (float)p * invf;          // f32 product, like the reference einsum
    g_cos[t] = (float)cos((double)ang);
    g_sin[t] = (float)sin((double)ang);
}

// ---------------- Mask dtype sniffing + conversion ---------------------------
__global__ void sniff_kernel(const unsigned char* m) {
    __shared__ int f[3];
    if (threadIdx.x < 3) f[threadIdx.x] = 0;
    __syncthreads();
    int a = 0, b = 0, c = 0;
    for (int i = threadIdx.x; i < Bb * Tn; i += 256) {
        unsigned v = m[i];
        if (v > 1) a = 1;
        if (v != 0 && (i & 3)) b = 1;
        if (v != 0 && ((i & 3) < 2)) c = 1;
    }
    if (a) atomicOr(&f[0], 1);
    if (b) atomicOr(&f[1], 1);
    if (c) atomicOr(&f[2], 1);
    __syncthreads();
    if (threadIdx.x == 0) {
        // no byte>1: u8 bools (nonzero at pos%4!=0) vs int32 0/1
        // byte>1 present: bf16 (nonzero at pos%4 in {0,1}) vs f32
        g_kind = (!f[0]) ? (f[1] ? 0 : 1) : (f[2] ? 3 : 2);
    }
}

__global__ void maskcvt_kernel(const void* m) {
    int i = blockIdx.x * 256 + threadIdx.x;
    if (i >= Bb * Tn) return;
    int k = g_kind;
    bool msk;
    if (k == 0)      msk = ((const unsigned char*)m)[i] != 0;
    else if (k == 1) msk = ((const int*)m)[i] != 0;
    else if (k == 2) msk = ((const float*)m)[i] != 0.0f;
    else             msk = __bfloat162float(((const __nv_bfloat16*)m)[i]) != 0.0f;
    g_maskf[i] = msk ? 1.0f : 0.0f;
}

// ---------------- SGEMM: C[M,N] = A[M,K] @ B[K,N], row-major, f32x2 inner ----
__global__ __launch_bounds__(256, 2) void sgemm_kernel(
    const float* __restrict__ A, const float* __restrict__ B,
    float* __restrict__ C, int M, int N, int K) {
    __shared__ float As[16 * 128];
    __shared__ float Bs[16 * 128];
    int tid = threadIdx.x, tx = tid & 15, ty = tid >> 4;
    int bm = blockIdx.y * 128, bn = blockIdx.x * 128;
    const float* Ap = A + (size_t)bm * K;
    const float* Bp = B + bn;
    float2 acc[8][4];
#pragma unroll
    for (int i = 0; i < 8; i++)
#pragma unroll
        for (int j = 0; j < 4; j++) acc[i][j] = make_float2(0.f, 0.f);

    for (int kt = 0; kt < K; kt += 16) {
#pragma unroll
        for (int r2 = 0; r2 < 2; r2++) {
            int idx = tid + r2 * 256;                 // 0..511
            int ar = idx >> 2, ac = (idx & 3) * 4;    // A tile 128x16
            float4 av = *(const float4*)&Ap[(size_t)ar * K + kt + ac];
            As[(ac + 0) * 128 + ar] = av.x;
            As[(ac + 1) * 128 + ar] = av.y;
            As[(ac + 2) * 128 + ar] = av.z;
            As[(ac + 3) * 128 + ar] = av.w;
            int br = idx >> 5, bc = (idx & 31) * 4;   // B tile 16x128
            *(float4*)&Bs[br * 128 + bc] = *(const float4*)&Bp[(size_t)(kt + br) * N + bc];
        }
        __syncthreads();
#pragma unroll
        for (int kk = 0; kk < 16; kk++) {
            float4 a0 = *(float4*)&As[kk * 128 + ty * 8];
            float4 a1 = *(float4*)&As[kk * 128 + ty * 8 + 4];
            float4 b0 = *(float4*)&Bs[kk * 128 + tx * 4];
            float4 b1 = *(float4*)&Bs[kk * 128 + tx * 4 + 64];
            float2 bb0 = make_float2(b0.x, b0.y), bb1 = make_float2(b0.z, b0.w);
            float2 bb2 = make_float2(b1.x, b1.y), bb3 = make_float2(b1.z, b1.w);
            float aa[8] = {a0.x, a0.y, a0.z, a0.w, a1.x, a1.y, a1.z, a1.w};
#pragma unroll
            for (int i = 0; i < 8; i++) {
                float2 ad = make_float2(aa[i], aa[i]);
                acc[i][0] = ffma2(ad, bb0, acc[i][0]);
                acc[i][1] = ffma2(ad, bb1, acc[i][1]);
                acc[i][2] = ffma2(ad, bb2, acc[i][2]);
                acc[i][3] = ffma2(ad, bb3, acc[i][3]);
            }
        }
        __syncthreads();
    }
#pragma unroll
    for (int i = 0; i < 8; i++) {
        size_t row = bm + ty * 8 + i;
        *(float4*)&C[row * N + bn + tx * 4] =
            make_float4(acc[i][0].x, acc[i][0].y, acc[i][1].x, acc[i][1].y);
        *(float4*)&C[row * N + bn + tx * 4 + 64] =
            make_float4(acc[i][2].x, acc[i][2].y, acc[i][3].x, acc[i][3].y);
    }
}

// ---------------- RoPE apply (in place) --------------------------------------
__global__ void rope_kernel(float* buf, const int* __restrict__ pos) {
    int i = blockIdx.x * 256 + threadIdx.x;
    if (i >= NTOK * Hn * 64) return;
    int j = i & 63;
    int h = (i >> 6) & 15;
    int tok = i >> 10;
    int p = pos[tok];
    float c = g_cos[p * 64 + j], s = g_sin[p * 64 + j];
    size_t base = (size_t)tok * HDn + h * 128 + j;
    float q1 = buf[base], q2 = buf[base + 64];
    buf[base]      = q1 * c - q2 * s;
    buf[base + 64] = q2 * c + q1 * s;
}

// ---------------- Flash attention: 64q x 64k tiles, online softmax -----------
__global__ __launch_bounds__(256, 2) void attn_kernel(
    const float* __restrict__ Q, const float* __restrict__ K,
    const float* __restrict__ V, float* __restrict__ Y) {
    extern __shared__ float sm[];
    float* Qs     = sm;                 // 64*128
    float* KVs    = Qs + 64 * 128;      // 64*132
    float* Ss     = KVs + 64 * KVS;     // 64*68
    float* mrow   = Ss + 64 * SSD;
    float* lrow   = mrow + 64;
    float* salpha = lrow + 64;
    float* sflag  = salpha + 64;

    int tid = threadIdx.x, tx = tid & 15, ty = tid >> 4;
    int q0 = blockIdx.x * 64, h = blockIdx.y, b = blockIdx.z;
    size_t qbase = ((size_t)(b * TQn + q0)) * HDn + h * 128;
    size_t kbase = ((size_t)(b * Tn)) * HDn + h * 128;
    const float NI = neginf();

#pragma unroll
    for (int it = 0; it < 8; it++) {
        int idx = tid + it * 256;
        int r = idx >> 5, c = (idx & 31) * 4;
        *(float4*)&Qs[r * 128 + c] = *(const float4*)&Q[qbase + (size_t)r * HDn + c];
    }
    if (tid < 64) { mrow[tid] = NI; lrow[tid] = 0.f; }
    float2 oacc[4][4];
#pragma unroll
    for (int i = 0; i < 4; i++)
#pragma unroll
        for (int q = 0; q < 4; q++) oacc[i][q] = make_float2(0.f, 0.f);
    const float scale = 0.088388347648318447f;   // 1/sqrt(128)

    for (int kt = 0; kt < Tn; kt += 64) {
        // (A) K tile + mask flags
#pragma unroll
        for (int it = 0; it < 8; it++) {
            int idx = tid + it * 256;
            int r = idx >> 5, c = (idx & 31) * 4;
            *(float4*)&KVs[r * KVS + c] = *(const float4*)&K[kbase + (size_t)(kt + r) * HDn + c];
        }
        if (tid < 64) sflag[tid] = g_maskf[b * Tn + kt + tid];
        __syncthreads();

        // (B) S = Q @ K^T (scaled), dot-product f32x2
        float2 sa[4][4];
#pragma unroll
        for (int i = 0; i < 4; i++)
#pragma unroll
            for (int j = 0; j < 4; j++) sa[i][j] = make_float2(0.f, 0.f);
#pragma unroll
        for (int d = 0; d < 128; d += 4) {
            float4 q4[4], k4[4];
#pragma unroll
            for (int i = 0; i < 4; i++) q4[i] = *(float4*)&Qs[(ty * 4 + i) * 128 + d];
#pragma unroll
            for (int j = 0; j < 4; j++) k4[j] = *(float4*)&KVs[(tx * 4 + j) * KVS + d];
#pragma unroll
            for (int i = 0; i < 4; i++)
#pragma unroll
                for (int j = 0; j < 4; j++) {
                    sa[i][j] = ffma2(make_float2(q4[i].x, q4[i].y),
                                     make_float2(k4[j].x, k4[j].y), sa[i][j]);
                    sa[i][j] = ffma2(make_float2(q4[i].z, q4[i].w),
                                     make_float2(k4[j].z, k4[j].w), sa[i][j]);
                }
        }
#pragma unroll
        for (int i = 0; i < 4; i++) {
            float4 sv = make_float4((sa[i][0].x + sa[i][0].y) * scale,
                                    (sa[i][1].x + sa[i][1].y) * scale,
                                    (sa[i][2].x + sa[i][2].y) * scale,
                                    (sa[i][3].x + sa[i][3].y) * scale);
            *(float4*)&Ss[(ty * 4 + i) * SSD + tx * 4] = sv;
        }
        __syncthreads();

        // (C) row owners: running max + alpha
        if (tid < 64) {
            float m = NI;
            for (int j = 0; j < 64; j++)
                if (sflag[j] == 0.f) m = fmaxf(m, Ss[tid * SSD + j]);
            float mo = mrow[tid];
            float mn = fmaxf(mo, m);
            salpha[tid] = (mo > NI) ? __expf(mo - mn) : 1.0f;
            mrow[tid] = mn;
        }
        __syncthreads();

        // (D) all threads: P = exp(S - m) with masking; load V tile
#pragma unroll
        for (int i = 0; i < 4; i++) {
            int row = ty * 4 + i;
            float mn = mrow[row];
            float4 sv = *(float4*)&Ss[row * SSD + tx * 4];
            float4 pv;
            pv.x = (sflag[tx * 4 + 0] != 0.f || mn == NI) ? 0.f : __expf(sv.x - mn);
            pv.y = (sflag[tx * 4 + 1] != 0.f || mn == NI) ? 0.f : __expf(sv.y - mn);
            pv.z = (sflag[tx * 4 + 2] != 0.f || mn == NI) ? 0.f : __expf(sv.z - mn);
            pv.w = (sflag[tx * 4 + 3] != 0.f || mn == NI) ? 0.f : __expf(sv.w - mn);
            *(float4*)&Ss[row * SSD + tx * 4] = pv;
        }
#pragma unroll
        for (int it = 0; it < 8; it++) {
            int idx = tid + it * 256;
            int r = idx >> 5, c = (idx & 31) * 4;
            *(float4*)&KVs[r * KVS + c] = *(const float4*)&V[kbase + (size_t)(kt + r) * HDn + c];
        }
        __syncthreads();

        // (E) owners: l update; all: O = O*alpha + P @ V (f32x2)
        if (tid < 64) {
            float s_ = 0.f;
            for (int j = 0; j < 64; j++) s_ += Ss[tid * SSD + j];
            lrow[tid] = lrow[tid] * salpha[tid] + s_;
        }
#pragma unroll
        for (int i = 0; i < 4; i++) {
            float al = salpha[ty * 4 + i];
#pragma unroll
            for (int q = 0; q < 4; q++) { oacc[i][q].x *= al; oacc[i][q].y *= al; }
        }
        for (int j = 0; j < 64; j++) {
            float4 v0 = *(float4*)&KVs[j * KVS + tx * 4];
            float4 v1 = *(float4*)&KVs[j * KVS + tx * 4 + 64];
            float2 vv0 = make_float2(v0.x, v0.y), vv1 = make_float2(v0.z, v0.w);
            float2 vv2 = make_float2(v1.x, v1.y), vv3 = make_float2(v1.z, v1.w);
#pragma unroll
            for (int i = 0; i < 4; i++) {
                float p = Ss[(ty * 4 + i) * SSD + j];
                float2 pp = make_float2(p, p);
                oacc[i][0] = ffma2(pp, vv0, oacc[i][0]);
                oacc[i][1] = ffma2(pp, vv1, oacc[i][1]);
                oacc[i][2] = ffma2(pp, vv2, oacc[i][2]);
                oacc[i][3] = ffma2(pp, vv3, oacc[i][3]);
            }
        }
        __syncthreads();
    }

#pragma unroll
    for (int i = 0; i < 4; i++) {
        int row = ty * 4 + i;
        float linv = 1.0f / lrow[row];
        size_t orow = qbase + (size_t)row * HDn;
        *(float4*)&Y[orow + tx * 4] =
            make_float4(oacc[i][0].x * linv, oacc[i][0].y * linv,
                        oacc[i][1].x * linv, oacc[i][1].y * linv);
        *(float4*)&Y[orow + tx * 4 + 64] =
            make_float4(oacc[i][2].x * linv, oacc[i][2].y * linv,
                        oacc[i][3].x * linv, oacc[i][3].y * linv);
    }
}

#define ATTN_SMEM ((64 * 128 + 64 * KVS + 64 * SSD + 256) * 4)

extern "C" void kernel_launch(void* const* d_in, const int* in_sizes, int n_in,
                              void* d_out, int out_size) {
    const float* x       = (const float*)d_in[0];
    const float* xall    = (const float*)d_in[1];
    const int*   posx    = (const int*)d_in[2];
    const int*   posxall = (const int*)d_in[3];
    const void*  mask    = d_in[4];
    const float* Wq      = (const float*)d_in[5];
    const float* Wk      = (const float*)d_in[6];
    const float* Wv      = (const float*)d_in[7];
    const float* Wo      = (const float*)d_in[8];
    float* out = (float*)d_out;

    float *Qp, *Kp, *Vp, *Yp;
    cudaGetSymbolAddress((void**)&Qp, g_Q);
    cudaGetSymbolAddress((void**)&Kp, g_K);
    cudaGetSymbolAddress((void**)&Vp, g_V);
    cudaGetSymbolAddress((void**)&Yp, g_Y);

    cudaFuncSetAttribute(attn_kernel, cudaFuncAttributeMaxDynamicSharedMemorySize, ATTN_SMEM);

    ropetab_kernel<<<(POSN * 64 + 255) / 256, 256>>>();
    sniff_kernel<<<1, 256>>>((const unsigned char*)mask);
    maskcvt_kernel<<<(Bb * Tn + 255) / 256, 256>>>(mask);

    dim3 gp(HDn / 128, NTOK / 128);
    sgemm_kernel<<<gp, 256>>>(x,    Wq, Qp, NTOK, HDn, En);
    sgemm_kernel<<<gp, 256>>>(xall, Wk, Kp, NTOK, HDn, En);
    sgemm_kernel<<<gp, 256>>>(xall, Wv, Vp, NTOK, HDn, En);

    rope_kernel<<<(NTOK * Hn * 64 + 255) / 256, 256>>>(Qp, posx);
    rope_kernel<<<(NTOK * Hn * 64 + 255) / 256, 256>>>(Kp, posxall);

    dim3 ga(TQn / 64, Hn, Bb);
    attn_kernel<<<ga, 256, ATTN_SMEM>>>(Qp, Kp, Vp, Yp);

    dim3 go(En / 128, NTOK / 128);
    sgemm_kernel<<<go, 256>>>(Yp, Wo, out, NTOK, En, HDn);
}

// round 7
// speedup vs baseline: 4.3888x; 4.3888x over previous
#include <cuda_runtime.h>
#include <cuda_bf16.h>
#include <math.h>
#include <stdint.h>

#define Bb 4
#define TQn 2048
#define Tn 2048
#define En 2048
#define Hn 16
#define Dn 128
#define HDn 2048
#define NTOK 8192
#define POSN 4096

// ---------------- scratch ----------------------------------------------------
__device__ float g_Q[(size_t)NTOK * HDn];
__device__ float g_K[(size_t)NTOK * HDn];
__device__ float g_V[(size_t)NTOK * HDn];
__device__ float g_Y[(size_t)NTOK * HDn];
__device__ float g_cos[POSN * 64];
__device__ float g_sin[POSN * 64];
__device__ float g_maskf[Bb * Tn];
__device__ int   g_kind;

__device__ __nv_bfloat16 g_xhi[(size_t)NTOK * En];
__device__ __nv_bfloat16 g_xlo[(size_t)NTOK * En];
__device__ __nv_bfloat16 g_ahi[(size_t)NTOK * En];
__device__ __nv_bfloat16 g_alo[(size_t)NTOK * En];
__device__ __nv_bfloat16 g_qhi[(size_t)NTOK * HDn];
__device__ __nv_bfloat16 g_qlo[(size_t)NTOK * HDn];
__device__ __nv_bfloat16 g_khi[(size_t)NTOK * HDn];
__device__ __nv_bfloat16 g_klo[(size_t)NTOK * HDn];
__device__ __nv_bfloat16 g_vhi[(size_t)NTOK * HDn];
__device__ __nv_bfloat16 g_vlo[(size_t)NTOK * HDn];
__device__ __nv_bfloat16 g_yhi[(size_t)NTOK * HDn];
__device__ __nv_bfloat16 g_ylo[(size_t)NTOK * HDn];
__device__ __nv_bfloat16 g_wqh[(size_t)En * HDn];
__device__ __nv_bfloat16 g_wql[(size_t)En * HDn];
__device__ __nv_bfloat16 g_wkh[(size_t)En * HDn];
__device__ __nv_bfloat16 g_wkl[(size_t)En * HDn];
__device__ __nv_bfloat16 g_wvh[(size_t)En * HDn];
__device__ __nv_bfloat16 g_wvl[(size_t)En * HDn];
__device__ __nv_bfloat16 g_woh[(size_t)En * HDn];
__device__ __nv_bfloat16 g_wol[(size_t)En * HDn];

// ---------------- helpers ----------------------------------------------------
__device__ __forceinline__ float neginf() { return __int_as_float(0xff800000u); }

__device__ __forceinline__ uint32_t smem_u32(const void* p) {
    uint32_t a;
    asm("{ .reg .u64 t; cvta.to.shared.u64 t, %1; cvt.u32.u64 %0, t; }" : "=r"(a) : "l"(p));
    return a;
}

__device__ __forceinline__ void mma16816(float* d, const uint32_t* a, const uint32_t* b) {
    asm volatile("mma.sync.aligned.m16n8k16.row.col.f32.bf16.bf16.f32 "
        "{%0,%1,%2,%3}, {%4,%5,%6,%7}, {%8,%9}, {%0,%1,%2,%3};"
        : "+f"(d[0]), "+f"(d[1]), "+f"(d[2]), "+f"(d[3])
        : "r"(a[0]), "r"(a[1]), "r"(a[2]), "r"(a[3]), "r"(b[0]), "r"(b[1]));
}
__device__ __forceinline__ void ldm4(uint32_t* r, uint32_t a) {
    asm volatile("ldmatrix.sync.aligned.m8n8.x4.shared.b16 {%0,%1,%2,%3}, [%4];"
        : "=r"(r[0]), "=r"(r[1]), "=r"(r[2]), "=r"(r[3]) : "r"(a));
}
__device__ __forceinline__ void ldm4t(uint32_t* r, uint32_t a) {
    asm volatile("ldmatrix.sync.aligned.m8n8.x4.trans.shared.b16 {%0,%1,%2,%3}, [%4];"
        : "=r"(r[0]), "=r"(r[1]), "=r"(r[2]), "=r"(r[3]) : "r"(a));
}
__device__ __forceinline__ void cpa16(uint32_t d, const void* s) {
    asm volatile("cp.async.cg.shared.global [%0], [%1], 16;" :: "r"(d), "l"(s));
}
#define CP_COMMIT() asm volatile("cp.async.commit_group;" ::: "memory")
#define CP_WAIT1()  asm volatile("cp.async.wait_group 1;" ::: "memory")

// split two fp32 into packed bf16x2 hi and lo parts
__device__ __forceinline__ void split2(float a, float b, uint32_t& hi, uint32_t& lo) {
    __nv_bfloat162 h;
    h.x = __float2bfloat16(a); h.y = __float2bfloat16(b);
    hi = *(uint32_t*)&h;
    __nv_bfloat162 l2;
    l2.x = __float2bfloat16(a - __bfloat162float(h.x));
    l2.y = __float2bfloat16(b - __bfloat162float(h.y));
    lo = *(uint32_t*)&l2;
}

// ---------------- small kernels ---------------------------------------------
__global__ void ropetab_kernel() {
    int t = blockIdx.x * 256 + threadIdx.x;
    if (t >= POSN * 64) return;
    int j = t & 63, p = t >> 6;
    double inv = 1.0 / pow(10000.0, (double)(2 * j) / 128.0);
    float invf = (float)inv;
    float ang = (float)p * invf;
    g_cos[t] = (float)cos((double)ang);
    g_sin[t] = (float)sin((double)ang);
}

__global__ void sniff_kernel(const unsigned char* m) {
    __shared__ int f[3];
    if (threadIdx.x < 3) f[threadIdx.x] = 0;
    __syncthreads();
    int a = 0, b = 0, c = 0;
    for (int i = threadIdx.x; i < Bb * Tn; i += 256) {
        unsigned v = m[i];
        if (v > 1) a = 1;
        if (v != 0 && (i & 3)) b = 1;
        if (v != 0 && ((i & 3) < 2)) c = 1;
    }
    if (a) atomicOr(&f[0], 1);
    if (b) atomicOr(&f[1], 1);
    if (c) atomicOr(&f[2], 1);
    __syncthreads();
    if (threadIdx.x == 0)
        g_kind = (!f[0]) ? (f[1] ? 0 : 1) : (f[2] ? 3 : 2);
}

__global__ void maskcvt_kernel(const void* m) {
    int i = blockIdx.x * 256 + threadIdx.x;
    if (i >= Bb * Tn) return;
    int k = g_kind;
    bool msk;
    if (k == 0)      msk = ((const unsigned char*)m)[i] != 0;
    else if (k == 1) msk = ((const int*)m)[i] != 0;
    else if (k == 2) msk = ((const float*)m)[i] != 0.0f;
    else             msk = __bfloat162float(((const __nv_bfloat16*)m)[i]) != 0.0f;
    g_maskf[i] = msk ? 1.0f : 0.0f;
}

__global__ void split_kernel(const float* __restrict__ in,
                             __nv_bfloat16* __restrict__ hi,
                             __nv_bfloat16* __restrict__ lo, int n4) {
    int i = blockIdx.x * 256 + threadIdx.x;
    if (i >= n4) return;
    float4 v = ((const float4*)in)[i];
    __nv_bfloat16 h0 = __float2bfloat16(v.x), h1 = __float2bfloat16(v.y);
    __nv_bfloat16 h2 = __float2bfloat16(v.z), h3 = __float2bfloat16(v.w);
    __nv_bfloat162 H0, H1, L0, L1;
    H0.x = h0; H0.y = h1; H1.x = h2; H1.y = h3;
    L0.x = __float2bfloat16(v.x - __bfloat162float(h0));
    L0.y = __float2bfloat16(v.y - __bfloat162float(h1));
    L1.x = __float2bfloat16(v.z - __bfloat162float(h2));
    L1.y = __float2bfloat16(v.w - __bfloat162float(h3));
    ((__nv_bfloat162*)hi)[i * 2]     = H0;
    ((__nv_bfloat162*)hi)[i * 2 + 1] = H1;
    ((__nv_bfloat162*)lo)[i * 2]     = L0;
    ((__nv_bfloat162*)lo)[i * 2 + 1] = L1;
}

// W[K][N] -> Wt[N][K] bf16 hi/lo
__global__ void splitT_kernel(const float* __restrict__ W,
                              __nv_bfloat16* __restrict__ hi,
                              __nv_bfloat16* __restrict__ lo) {
    __shared__ float t[32][33];
    int n0 = blockIdx.x * 32, k0 = blockIdx.y * 32;
    for (int r = threadIdx.y; r < 32; r += 8)
        t[r][threadIdx.x] = W[(size_t)(k0 + r) * 2048 + n0 + threadIdx.x];
    __syncthreads();
    for (int r = threadIdx.y; r < 32; r += 8) {
        float v = t[threadIdx.x][r];
        __nv_bfloat16 h = __float2bfloat16(v);
        size_t o = (size_t)(n0 + r) * 2048 + k0 + threadIdx.x;
        hi[o] = h;
        lo[o] = __float2bfloat16(v - __bfloat162float(h));
    }
}

// rope (fp32 in) -> bf16 hi/lo out
__global__ void rope_split_kernel(const float* __restrict__ buf,
                                  const int* __restrict__ pos,
                                  __nv_bfloat16* __restrict__ oh,
                                  __nv_bfloat16* __restrict__ ol) {
    int i = blockIdx.x * 256 + threadIdx.x;
    if (i >= NTOK * Hn * 64) return;
    int j = i & 63;
    int h = (i >> 6) & 15;
    int tok = i >> 10;
    int p = pos[tok];
    float c = g_cos[p * 64 + j], s = g_sin[p * 64 + j];
    size_t base = (size_t)tok * HDn + h * 128 + j;
    float q1 = buf[base], q2 = buf[base + 64];
    float r1 = q1 * c - q2 * s;
    float r2 = q2 * c + q1 * s;
    __nv_bfloat16 h1 = __float2bfloat16(r1);
    __nv_bfloat16 h2 = __float2bfloat16(r2);
    oh[base] = h1;       ol[base]      = __float2bfloat16(r1 - __bfloat162float(h1));
    oh[base + 64] = h2;  ol[base + 64] = __float2bfloat16(r2 - __bfloat162float(h2));
}

// ---------------- HMMA bf16x3 GEMM -------------------------------------------
// C[M,N] = A[M,K] @ W[K,N]; A as (Ahi,Alo)[M,K] row-major, W as (Bhi,Blo)[N,K].
#define GROW 80         // padded row stride (bytes) for 32-elem bf16 rows
#define GTILE 10240     // 128 rows * 80B
#define GST  40960      // stage = 4 tiles
#define GSMEM (3 * GST)

__global__ __launch_bounds__(256, 1) void bgemm_kernel(
    const __nv_bfloat16* __restrict__ Ahi, const __nv_bfloat16* __restrict__ Alo,
    const __nv_bfloat16* __restrict__ Bhi, const __nv_bfloat16* __restrict__ Blo,
    float* __restrict__ C, int M, int N, int K) {
    extern __shared__ __align__(128) char gsm[];
    uint32_t sb = smem_u32(gsm);
    int tid = threadIdx.x, lane = tid & 31, wid = tid >> 5;
    int wm = wid & 1, wn = wid >> 1;
    size_t bm = (size_t)blockIdx.y * 128, bn = (size_t)blockIdx.x * 128;

    // per-thread copy slots (8 chunks of 16B per stage)
    const __nv_bfloat16* srcb[8];
    uint32_t dstb[8];
#pragma unroll
    for (int i = 0; i < 8; i++) {
        int id = tid + i * 256, tile = id >> 9, w = id & 511, row = w >> 2, c = w & 3;
        const __nv_bfloat16* base = (tile == 0) ? Ahi : (tile == 1) ? Alo
                                  : (tile == 2) ? Bhi : Blo;
        size_t grow = ((tile < 2) ? bm : bn) + row;
        srcb[i] = base + grow * (size_t)K + c * 8;
        dstb[i] = sb + tile * GTILE + row * GROW + c * 16;
    }

    float acc[4][4][4];
#pragma unroll
    for (int a = 0; a < 4; a++)
#pragma unroll
        for (int b = 0; b < 4; b++)
#pragma unroll
            for (int c = 0; c < 4; c++) acc[a][b][c] = 0.f;

    const int NT = K / 32;
    // prologue
#pragma unroll
    for (int s = 0; s < 2; s++) {
#pragma unroll
        for (int i = 0; i < 8; i++) cpa16(dstb[i] + s * GST, srcb[i] + s * 32);
        CP_COMMIT();
    }

    for (int kt = 0; kt < NT; kt++) {
        CP_WAIT1();
        __syncthreads();
        if (kt + 2 < NT) {
            uint32_t so = ((kt + 2) % 3) * GST;
#pragma unroll
            for (int i = 0; i < 8; i++) cpa16(dstb[i] + so, srcb[i] + (kt + 2) * 32);
        }
        CP_COMMIT();

        uint32_t st = sb + (kt % 3) * GST;
        uint32_t arow = st + (wm * 64 + (lane & 15)) * GROW + ((lane >> 4) << 4);
        uint32_t brow = st + 2 * GTILE +
                        (wn * 32 + (lane & 7) + ((lane >> 4) << 3)) * GROW +
                        (((lane >> 3) & 1) << 4);
#pragma unroll
        for (int kf = 0; kf < 2; kf++) {
            uint32_t ah[4][4], al[4][4];
#pragma unroll
            for (int mi = 0; mi < 4; mi++) {
                ldm4(ah[mi], arow + mi * 16 * GROW + kf * 32);
                ldm4(al[mi], arow + GTILE + mi * 16 * GROW + kf * 32);
            }
#pragma unroll
            for (int njp = 0; njp < 2; njp++) {
                uint32_t bh[4], bl[4];
                ldm4(bh, brow + njp * 16 * GROW + kf * 32);
                ldm4(bl, brow + GTILE + njp * 16 * GROW + kf * 32);
#pragma unroll
                for (int mi = 0; mi < 4; mi++) {
                    mma16816(acc[mi][2 * njp],     ah[mi], bh);
                    mma16816(acc[mi][2 * njp],     ah[mi], bl);
                    mma16816(acc[mi][2 * njp],     al[mi], bh);
                    mma16816(acc[mi][2 * njp + 1], ah[mi], bh + 2);
                    mma16816(acc[mi][2 * njp + 1], ah[mi], bl + 2);
                    mma16816(acc[mi][2 * njp + 1], al[mi], bh + 2);
                }
            }
        }
        __syncthreads();
    }

#pragma unroll
    for (int mi = 0; mi < 4; mi++)
#pragma unroll
        for (int nj = 0; nj < 4; nj++) {
            size_t r0 = bm + wm * 64 + mi * 16 + (lane >> 2);
            size_t cc = bn + wn * 32 + nj * 8 + (lane & 3) * 2;
            *(float2*)&C[r0 * N + cc]       = make_float2(acc[mi][nj][0], acc[mi][nj][1]);
            *(float2*)&C[(r0 + 8) * N + cc] = make_float2(acc[mi][nj][2], acc[mi][nj][3]);
        }
}

// ---------------- HMMA flash attention ---------------------------------------
#define ATQ 272          // padded row stride (bytes): 128 bf16 + pad
#define S_QH 0
#define S_QL 17408
#define S_KH 34816
#define S_KL 52224
#define S_FLG 69632
#define ATTN_SMEM 69896

__global__ __launch_bounds__(128) void attn_kernel(
    const __nv_bfloat16* __restrict__ Qh, const __nv_bfloat16* __restrict__ Ql,
    const __nv_bfloat16* __restrict__ Kh, const __nv_bfloat16* __restrict__ Kl,
    const __nv_bfloat16* __restrict__ Vh, const __nv_bfloat16* __restrict__ Vl,
    float* __restrict__ Y) {
    extern __shared__ __align__(128) char ash[];
    uint32_t sb = smem_u32(ash);
    int tid = threadIdx.x, lane = tid & 31, w = tid >> 5;
    int qb = blockIdx.x * 64, h = blockIdx.y, b = blockIdx.z;
    size_t tok0 = (size_t)b * TQn + qb;
    size_t ktok0 = (size_t)b * Tn;
    int hcol = h * 128;
    const float NI = neginf();
    const float scale = 0.08838834764831845f;

    // load Q tile (hi+lo)
#pragma unroll
    for (int i = 0; i < 16; i++) {
        int id = tid + i * 128;
        int buf = id >> 10, ww = id & 1023, row = ww >> 4, c = ww & 15;
        const __nv_bfloat16* src = (buf ? Ql : Qh) + (tok0 + row) * HDn + hcol + c * 8;
        *(uint4*)(ash + (buf ? S_QL : S_QH) + row * ATQ + c * 16) = *(const uint4*)src;
    }
    __syncthreads();

    // Q fragments (8 k16 frags, hi+lo)
    uint32_t qhf[8][4], qlf[8][4];
    {
        uint32_t abase = sb + (w * 16 + (lane & 15)) * ATQ + ((lane >> 4) << 4);
#pragma unroll
        for (int kf = 0; kf < 8; kf++) {
            ldm4(qhf[kf], abase + kf * 32);
            ldm4(qlf[kf], abase + S_QL + kf * 32);
        }
    }
    __syncthreads();

    float oa[16][4];
#pragma unroll
    for (int i = 0; i < 16; i++)
#pragma unroll
        for (int j = 0; j < 4; j++) oa[i][j] = 0.f;
    float m_a = NI, m_b = NI, l_a = 0.f, l_b = 0.f;

    for (int kt = 0; kt < Tn / 64; kt++) {
        // K tile
#pragma unroll
        for (int i = 0; i < 16; i++) {
            int id = tid + i * 128;
            int buf = id >> 10, ww = id & 1023, row = ww >> 4, c = ww & 15;
            const __nv_bfloat16* src = (buf ? Kl : Kh) +
                (ktok0 + kt * 64 + row) * HDn + hcol + c * 8;
            *(uint4*)(ash + (buf ? S_KL : S_KH) + row * ATQ + c * 16) = *(const uint4*)src;
        }
        if (tid < 64) *(float*)(ash + S_FLG + tid * 4) = g_maskf[b * Tn + kt * 64 + tid];
        __syncthreads();

        // S = Q K^T
        float sc[8][4];
#pragma unroll
        for (int i = 0; i < 8; i++)
#pragma unroll
            for (int j = 0; j < 4; j++) sc[i][j] = 0.f;
        {
            uint32_t bbase = sb + S_KH +
                ((lane & 7) + ((lane >> 4) << 3)) * ATQ + (((lane >> 3) & 1) << 4);
#pragma unroll
            for (int kf = 0; kf < 8; kf++) {
#pragma unroll
                for (int njp = 0; njp < 4; njp++) {
                    uint32_t kh4[4], kl4[4];
                    ldm4(kh4, bbase + njp * 16 * ATQ + kf * 32);
                    ldm4(kl4, bbase + (S_KL - S_KH) + njp * 16 * ATQ + kf * 32);
                    mma16816(sc[2 * njp],     qhf[kf], kh4);
                    mma16816(sc[2 * njp],     qhf[kf], kl4);
                    mma16816(sc[2 * njp],     qlf[kf], kh4);
                    mma16816(sc[2 * njp + 1], qhf[kf], kh4 + 2);
                    mma16816(sc[2 * njp + 1], qhf[kf], kl4 + 2);
                    mma16816(sc[2 * njp + 1], qlf[kf], kh4 + 2);
                }
            }
        }

        // softmax update (rows owned in-warp)
        const float* flg = (const float*)(ash + S_FLG);
        float f0[8], f1[8];
        float ta = NI, tb = NI;
#pragma unroll
        for (int nf = 0; nf < 8; nf++) {
            f0[nf] = flg[nf * 8 + (lane & 3) * 2];
            f1[nf] = flg[nf * 8 + (lane & 3) * 2 + 1];
#pragma unroll
            for (int j = 0; j < 4; j++) sc[nf][j] *= scale;
            if (f0[nf] == 0.f) { ta = fmaxf(ta, sc[nf][0]); tb = fmaxf(tb, sc[nf][2]); }
            if (f1[nf] == 0.f) { ta = fmaxf(ta, sc[nf][1]); tb = fmaxf(tb, sc[nf][3]); }
        }
        ta = fmaxf(ta, __shfl_xor_sync(0xffffffffu, ta, 1));
        ta = fmaxf(ta, __shfl_xor_sync(0xffffffffu, ta, 2));
        tb = fmaxf(tb, __shfl_xor_sync(0xffffffffu, tb, 1));
        tb = fmaxf(tb, __shfl_xor_sync(0xffffffffu, tb, 2));
        float mna = fmaxf(m_a, ta), mnb = fmaxf(m_b, tb);
        float alpha_a = (m_a > NI) ? __expf(m_a - mna) : 1.f;
        float alpha_b = (m_b > NI) ? __expf(m_b - mnb) : 1.f;
        m_a = mna; m_b = mnb;

        float sa = 0.f, sbm = 0.f;
#pragma unroll
        for (int nf = 0; nf < 8; nf++) {
            float p0 = (f0[nf] != 0.f || m_a == NI) ? 0.f : __expf(sc[nf][0] - m_a);
            float p1 = (f1[nf] != 0.f || m_a == NI) ? 0.f : __expf(sc[nf][1] - m_a);
            float p2 = (f0[nf] != 0.f || m_b == NI) ? 0.f : __expf(sc[nf][2] - m_b);
            float p3 = (f1[nf] != 0.f || m_b == NI) ? 0.f : __expf(sc[nf][3] - m_b);
            sc[nf][0] = p0; sc[nf][1] = p1; sc[nf][2] = p2; sc[nf][3] = p3;
            sa += p0 + p1; sbm += p2 + p3;
        }
        sa  += __shfl_xor_sync(0xffffffffu, sa, 1);
        sa  += __shfl_xor_sync(0xffffffffu, sa, 2);
        sbm += __shfl_xor_sync(0xffffffffu, sbm, 1);
        sbm += __shfl_xor_sync(0xffffffffu, sbm, 2);
        l_a = l_a * alpha_a + sa;
        l_b = l_b * alpha_b + sbm;
#pragma unroll
        for (int nf = 0; nf < 16; nf++) {
            oa[nf][0] *= alpha_a; oa[nf][1] *= alpha_a;
            oa[nf][2] *= alpha_b; oa[nf][3] *= alpha_b;
        }
        __syncthreads();   // all warps done reading K

        // V tile (overwrites K buffers)
#pragma unroll
        for (int i = 0; i < 16; i++) {
            int id = tid + i * 128;
            int buf = id >> 10, ww = id & 1023, row = ww >> 4, c = ww & 15;
            const __nv_bfloat16* src = (buf ? Vl : Vh) +
                (ktok0 + kt * 64 + row) * HDn + hcol + c * 8;
            *(uint4*)(ash + (buf ? S_KL : S_KH) + row * ATQ + c * 16) = *(const uint4*)src;
        }
        // P fragments while copy lands
        uint32_t ph[4][4], pl[4][4];
#pragma unroll
        for (int t = 0; t < 4; t++) {
            split2(sc[2 * t][0],     sc[2 * t][1],     ph[t][0], pl[t][0]);
            split2(sc[2 * t][2],     sc[2 * t][3],     ph[t][1], pl[t][1]);
            split2(sc[2 * t + 1][0], sc[2 * t + 1][1], ph[t][2], pl[t][2]);
            split2(sc[2 * t + 1][2], sc[2 * t + 1][3], ph[t][3], pl[t][3]);
        }
        __syncthreads();

        // O += P V
        {
            uint32_t vbase = sb + S_KH +
                ((lane & 7) + (((lane >> 3) & 1) << 3)) * ATQ + ((lane >> 4) << 4);
#pragma unroll
            for (int t = 0; t < 4; t++) {
#pragma unroll
                for (int njp = 0; njp < 8; njp++) {
                    uint32_t vh4[4], vl4[4];
                    ldm4t(vh4, vbase + t * 16 * ATQ + njp * 32);
                    ldm4t(vl4, vbase + (S_KL - S_KH) + t * 16 * ATQ + njp * 32);
                    int n0 = njp * 2, n1 = n0 + 1;
                    mma16816(oa[n0], ph[t], vh4);
                    mma16816(oa[n0], pl[t], vh4);
                    mma16816(oa[n0], ph[t], vl4);
                    mma16816(oa[n1], ph[t], vh4 + 2);
                    mma16816(oa[n1], pl[t], vh4 + 2);
                    mma16816(oa[n1], ph[t], vl4 + 2);
                }
            }
        }
        __syncthreads();   // done reading V before next K copy
    }

    float ia = 1.f / l_a, ib = 1.f / l_b;
    size_t ra = (tok0 + w * 16 + (lane >> 2)) * HDn + hcol + (lane & 3) * 2;
#pragma unroll
    for (int nf = 0; nf < 16; nf++) {
        *(float2*)&Y[ra + nf * 8] = make_float2(oa[nf][0] * ia, oa[nf][1] * ia);
        *(float2*)&Y[ra + 8 * HDn + nf * 8] = make_float2(oa[nf][2] * ib, oa[nf][3] * ib);
    }
}

// ---------------- launch -----------------------------------------------------
extern "C" void kernel_launch(void* const* d_in, const int* in_sizes, int n_in,
                              void* d_out, int out_size) {
    const float* x       = (const float*)d_in[0];
    const float* xall    = (const float*)d_in[1];
    const int*   posx    = (const int*)d_in[2];
    const int*   posxall = (const int*)d_in[3];
    const void*  mask    = d_in[4];
    const float* Wq      = (const float*)d_in[5];
    const float* Wk      = (const float*)d_in[6];
    const float* Wv      = (const float*)d_in[7];
    const float* Wo      = (const float*)d_in[8];
    float* out = (float*)d_out;

    float *Qp, *Kp, *Vp, *Yp;
    cudaGetSymbolAddress((void**)&Qp, g_Q);
    cudaGetSymbolAddress((void**)&Kp, g_K);
    cudaGetSymbolAddress((void**)&Vp, g_V);
    cudaGetSymbolAddress((void**)&Yp, g_Y);
    __nv_bfloat16 *xh, *xl, *ah, *al, *qh, *ql, *kh, *kl, *vh, *vl, *yh, *yl;
    __nv_bfloat16 *wqh, *wql, *wkh, *wkl, *wvh, *wvl, *woh, *wol;
    cudaGetSymbolAddress((void**)&xh, g_xhi);
    cudaGetSymbolAddress((void**)&xl, g_xlo);
    cudaGetSymbolAddress((void**)&ah, g_ahi);
    cudaGetSymbolAddress((void**)&al, g_alo);
    cudaGetSymbolAddress((void**)&qh, g_qhi);
    cudaGetSymbolAddress((void**)&ql, g_qlo);
    cudaGetSymbolAddress((void**)&kh, g_khi);
    cudaGetSymbolAddress((void**)&kl, g_klo);
    cudaGetSymbolAddress((void**)&vh, g_vhi);
    cudaGetSymbolAddress((void**)&vl, g_vlo);
    cudaGetSymbolAddress((void**)&yh, g_yhi);
    cudaGetSymbolAddress((void**)&yl, g_ylo);
    cudaGetSymbolAddress((void**)&wqh, g_wqh);
    cudaGetSymbolAddress((void**)&wql, g_wql);
    cudaGetSymbolAddress((void**)&wkh, g_wkh);
    cudaGetSymbolAddress((void**)&wkl, g_wkl);
    cudaGetSymbolAddress((void**)&wvh, g_wvh);
    cudaGetSymbolAddress((void**)&wvl, g_wvl);
    cudaGetSymbolAddress((void**)&woh, g_woh);
    cudaGetSymbolAddress((void**)&wol, g_wol);

    cudaFuncSetAttribute(bgemm_kernel, cudaFuncAttributeMaxDynamicSharedMemorySize, GSMEM);
    cudaFuncSetAttribute(attn_kernel, cudaFuncAttributeMaxDynamicSharedMemorySize, ATTN_SMEM);

    ropetab_kernel<<<(POSN * 64 + 255) / 256, 256>>>();
    sniff_kernel<<<1, 256>>>((const unsigned char*)mask);
    maskcvt_kernel<<<(Bb * Tn + 255) / 256, 256>>>(mask);

    const int NE4 = NTOK * En / 4;
    split_kernel<<<(NE4 + 255) / 256, 256>>>(x,    xh, xl, NE4);
    split_kernel<<<(NE4 + 255) / 256, 256>>>(xall, ah, al, NE4);
    dim3 gt(64, 64), bt(32, 8);
    splitT_kernel<<<gt, bt>>>(Wq, wqh, wql);
    splitT_kernel<<<gt, bt>>>(Wk, wkh, wkl);
    splitT_kernel<<<gt, bt>>>(Wv, wvh, wvl);
    splitT_kernel<<<gt, bt>>>(Wo, woh, wol);

    dim3 gg(HDn / 128, NTOK / 128);
    bgemm_kernel<<<gg, 256, GSMEM>>>(xh, xl, wqh, wql, Qp, NTOK, HDn, En);
    bgemm_kernel<<<gg, 256, GSMEM>>>(ah, al, wkh, wkl, Kp, NTOK, HDn, En);
    bgemm_kernel<<<gg, 256, GSMEM>>>(ah, al, wvh, wvl, Vp, NTOK, HDn, En);

    rope_split_kernel<<<(NTOK * Hn * 64 + 255) / 256, 256>>>(Qp, posx, qh, ql);
    rope_split_kernel<<<(NTOK * Hn * 64 + 255) / 256, 256>>>(Kp, posxall, kh, kl);
    split_kernel<<<(NE4 + 255) / 256, 256>>>(Vp, vh, vl, NE4);

    dim3 ga(TQn / 64, Hn, Bb);
    attn_kernel<<<ga, 128, ATTN_SMEM>>>(qh, ql, kh, kl, vh, vl, Yp);

    split_kernel<<<(NE4 + 255) / 256, 256>>>(Yp, yh, yl, NE4);
    bgemm_kernel<<<gg, 256, GSMEM>>>(yh, yl, woh, wol, out, NTOK, En, HDn);
}

// round 8
// speedup vs baseline: 7.0718x; 1.6113x over previous
#include <cuda_runtime.h>
#include <cuda_fp16.h>
#include <cuda_bf16.h>
#include <math.h>
#include <stdint.h>

#define Bb 4
#define TQn 2048
#define Tn 2048
#define En 2048
#define Hn 16
#define Dn 128
#define HDn 2048
#define NTOK 8192
#define POSN 4096

// ---------------- scratch ----------------------------------------------------
__device__ float g_Q[(size_t)NTOK * HDn];
__device__ float g_K[(size_t)NTOK * HDn];
__device__ float g_V[(size_t)NTOK * HDn];
__device__ float g_Y[(size_t)NTOK * HDn];
__device__ float g_cos[POSN * 64];
__device__ float g_sin[POSN * 64];
__device__ float g_maskf[Bb * Tn];
__device__ int   g_kind;

__device__ __half g_xh[(size_t)NTOK * En];
__device__ __half g_xl[(size_t)NTOK * En];
__device__ __half g_ah[(size_t)NTOK * En];
__device__ __half g_al[(size_t)NTOK * En];
__device__ __half g_qh[(size_t)NTOK * HDn];
__device__ __half g_ql[(size_t)NTOK * HDn];
__device__ __half g_kh[(size_t)NTOK * HDn];
__device__ __half g_vh[(size_t)NTOK * HDn];
__device__ __half g_yh[(size_t)NTOK * HDn];
__device__ __half g_yl[(size_t)NTOK * HDn];
__device__ __half g_wq[(size_t)En * HDn];
__device__ __half g_wk[(size_t)En * HDn];
__device__ __half g_wv[(size_t)En * HDn];
__device__ __half g_wo[(size_t)En * HDn];

// ---------------- helpers ----------------------------------------------------
__device__ __forceinline__ float neginf() { return __int_as_float(0xff800000u); }

__device__ __forceinline__ uint32_t smem_u32(const void* p) {
    uint32_t a;
    asm("{ .reg .u64 t; cvta.to.shared.u64 t, %1; cvt.u32.u64 %0, t; }" : "=r"(a) : "l"(p));
    return a;
}

__device__ __forceinline__ void mma16816(float* d, const uint32_t* a, const uint32_t* b) {
    asm volatile("mma.sync.aligned.m16n8k16.row.col.f32.f16.f16.f32 "
        "{%0,%1,%2,%3}, {%4,%5,%6,%7}, {%8,%9}, {%0,%1,%2,%3};"
        : "+f"(d[0]), "+f"(d[1]), "+f"(d[2]), "+f"(d[3])
        : "r"(a[0]), "r"(a[1]), "r"(a[2]), "r"(a[3]), "r"(b[0]), "r"(b[1]));
}
__device__ __forceinline__ void ldm4(uint32_t* r, uint32_t a) {
    asm volatile("ldmatrix.sync.aligned.m8n8.x4.shared.b16 {%0,%1,%2,%3}, [%4];"
        : "=r"(r[0]), "=r"(r[1]), "=r"(r[2]), "=r"(r[3]) : "r"(a));
}
__device__ __forceinline__ void ldm4t(uint32_t* r, uint32_t a) {
    asm volatile("ldmatrix.sync.aligned.m8n8.x4.trans.shared.b16 {%0,%1,%2,%3}, [%4];"
        : "=r"(r[0]), "=r"(r[1]), "=r"(r[2]), "=r"(r[3]) : "r"(a));
}
__device__ __forceinline__ void cpa16(uint32_t d, const void* s) {
    asm volatile("cp.async.cg.shared.global [%0], [%1], 16;" :: "r"(d), "l"(s));
}
#define CP_COMMIT() asm volatile("cp.async.commit_group;" ::: "memory")
#define CP_WAIT1()  asm volatile("cp.async.wait_group 1;" ::: "memory")

// split two fp32 into packed fp16x2 hi and lo
__device__ __forceinline__ void split2h(float a, float b, uint32_t& hi, uint32_t& lo) {
    __half2 h = __floats2half2_rn(a, b);
    hi = *(uint32_t*)&h;
    __half2 l = __floats2half2_rn(a - __low2float(h), b - __high2float(h));
    lo = *(uint32_t*)&l;
}

// ---------------- small kernels ---------------------------------------------
__global__ void ropetab_kernel() {
    int t = blockIdx.x * 256 + threadIdx.x;
    if (t >= POSN * 64) return;
    int j = t & 63, p = t >> 6;
    double inv = 1.0 / pow(10000.0, (double)(2 * j) / 128.0);
    float invf = (float)inv;
    float ang = (float)p * invf;
    g_cos[t] = (float)cos((double)ang);
    g_sin[t] = (float)sin((double)ang);
}

__global__ void sniff_kernel(const unsigned char* m) {
    __shared__ int f[3];
    if (threadIdx.x < 3) f[threadIdx.x] = 0;
    __syncthreads();
    int a = 0, b = 0, c = 0;
    for (int i = threadIdx.x; i < Bb * Tn; i += 256) {
        unsigned v = m[i];
        if (v > 1) a = 1;
        if (v != 0 && (i & 3)) b = 1;
        if (v != 0 && ((i & 3) < 2)) c = 1;
    }
    if (a) atomicOr(&f[0], 1);
    if (b) atomicOr(&f[1], 1);
    if (c) atomicOr(&f[2], 1);
    __syncthreads();
    if (threadIdx.x == 0)
        g_kind = (!f[0]) ? (f[1] ? 0 : 1) : (f[2] ? 3 : 2);
}

__global__ void maskcvt_kernel(const void* m) {
    int i = blockIdx.x * 256 + threadIdx.x;
    if (i >= Bb * Tn) return;
    int k = g_kind;
    bool msk;
    if (k == 0)      msk = ((const unsigned char*)m)[i] != 0;
    else if (k == 1) msk = ((const int*)m)[i] != 0;
    else if (k == 2) msk = ((const float*)m)[i] != 0.0f;
    else             msk = __bfloat162float(((const __nv_bfloat16*)m)[i]) != 0.0f;
    g_maskf[i] = msk ? 1.0f : 0.0f;
}

// fp32 -> fp16 hi/lo split
__global__ void splitH2_kernel(const float* __restrict__ in,
                               __half* __restrict__ hi, __half* __restrict__ lo,
                               int n4) {
    int i = blockIdx.x * 256 + threadIdx.x;
    if (i >= n4) return;
    float4 v = ((const float4*)in)[i];
    uint32_t h0, l0, h1, l1;
    split2h(v.x, v.y, h0, l0);
    split2h(v.z, v.w, h1, l1);
    ((uint32_t*)hi)[i * 2]     = h0;
    ((uint32_t*)hi)[i * 2 + 1] = h1;
    ((uint32_t*)lo)[i * 2]     = l0;
    ((uint32_t*)lo)[i * 2 + 1] = l1;
}

// fp32 -> fp16 single
__global__ void cvtH_kernel(const float* __restrict__ in,
                            __half* __restrict__ out, int n4) {
    int i = blockIdx.x * 256 + threadIdx.x;
    if (i >= n4) return;
    float4 v = ((const float4*)in)[i];
    __half2 a = __floats2half2_rn(v.x, v.y);
    __half2 b = __floats2half2_rn(v.z, v.w);
    ((uint32_t*)out)[i * 2]     = *(uint32_t*)&a;
    ((uint32_t*)out)[i * 2 + 1] = *(uint32_t*)&b;
}

// W[K][N] -> Wt[N][K] single fp16
__global__ void splitT_kernel(const float* __restrict__ W, __half* __restrict__ out) {
    __shared__ float t[32][33];
    int n0 = blockIdx.x * 32, k0 = blockIdx.y * 32;
    for (int r = threadIdx.y; r < 32; r += 8)
        t[r][threadIdx.x] = W[(size_t)(k0 + r) * 2048 + n0 + threadIdx.x];
    __syncthreads();
    for (int r = threadIdx.y; r < 32; r += 8)
        out[(size_t)(n0 + r) * 2048 + k0 + threadIdx.x] = __float2half(t[threadIdx.x][r]);
}

// rope -> fp16 hi/lo
__global__ void rope_splitH_kernel(const float* __restrict__ buf,
                                   const int* __restrict__ pos,
                                   __half* __restrict__ oh, __half* __restrict__ ol) {
    int i = blockIdx.x * 256 + threadIdx.x;
    if (i >= NTOK * Hn * 64) return;
    int j = i & 63;
    int h = (i >> 6) & 15;
    int tok = i >> 10;
    int p = pos[tok];
    float c = g_cos[p * 64 + j], s = g_sin[p * 64 + j];
    size_t base = (size_t)tok * HDn + h * 128 + j;
    float q1 = buf[base], q2 = buf[base + 64];
    float r1 = q1 * c - q2 * s;
    float r2 = q2 * c + q1 * s;
    __half h1 = __float2half(r1), h2 = __float2half(r2);
    oh[base] = h1;       ol[base]      = __float2half(r1 - __half2float(h1));
    oh[base + 64] = h2;  ol[base + 64] = __float2half(r2 - __half2float(h2));
}

// rope -> fp16 single
__global__ void rope_singleH_kernel(const float* __restrict__ buf,
                                    const int* __restrict__ pos,
                                    __half* __restrict__ oh) {
    int i = blockIdx.x * 256 + threadIdx.x;
    if (i >= NTOK * Hn * 64) return;
    int j = i & 63;
    int h = (i >> 6) & 15;
    int tok = i >> 10;
    int p = pos[tok];
    float c = g_cos[p * 64 + j], s = g_sin[p * 64 + j];
    size_t base = (size_t)tok * HDn + h * 128 + j;
    float q1 = buf[base], q2 = buf[base + 64];
    oh[base]      = __float2half(q1 * c - q2 * s);
    oh[base + 64] = __float2half(q2 * c + q1 * s);
}

// ---------------- HMMA fp16x2 GEMM -------------------------------------------
// C[M,N] = A[M,K] @ W[K,N]; A as (Ahi,Alo)[M,K], W as Bh[N,K] single fp16.
#define GROW 80
#define GTILE 10240
#define GST  30720      // stage = 3 tiles
#define GSMEM (3 * GST)

__global__ __launch_bounds__(256, 1) void bgemm_kernel(
    const __half* __restrict__ Ahi, const __half* __restrict__ Alo,
    const __half* __restrict__ Bh, float* __restrict__ C, int M, int N, int K) {
    extern __shared__ __align__(128) char gsm[];
    uint32_t sb = smem_u32(gsm);
    int tid = threadIdx.x, lane = tid & 31, wid = tid >> 5;
    int wm = wid & 1, wn = wid >> 1;
    size_t bm = (size_t)blockIdx.y * 128, bn = (size_t)blockIdx.x * 128;

    // 6 chunks of 16B per thread per stage (3 tiles x 128 rows x 4 chunks)
    const __half* srcb[6];
    uint32_t dstb[6];
#pragma unroll
    for (int i = 0; i < 6; i++) {
        int id = tid + i * 256, tile = id >> 9, w = id & 511, row = w >> 2, c = w & 3;
        const __half* base = (tile == 0) ? Ahi : (tile == 1) ? Alo : Bh;
        size_t grow = ((tile < 2) ? bm : bn) + row;
        srcb[i] = base + grow * (size_t)K + c * 8;
        dstb[i] = sb + tile * GTILE + row * GROW + c * 16;
    }

    float acc[4][4][4];
#pragma unroll
    for (int a = 0; a < 4; a++)
#pragma unroll
        for (int b = 0; b < 4; b++)
#pragma unroll
            for (int c = 0; c < 4; c++) acc[a][b][c] = 0.f;

    const int NT = K / 32;
#pragma unroll
    for (int s = 0; s < 2; s++) {
#pragma unroll
        for (int i = 0; i < 6; i++) cpa16(dstb[i] + s * GST, srcb[i] + s * 32);
        CP_COMMIT();
    }

    for (int kt = 0; kt < NT; kt++) {
        CP_WAIT1();
        __syncthreads();
        if (kt + 2 < NT) {
            uint32_t so = ((kt + 2) % 3) * GST;
#pragma unroll
            for (int i = 0; i < 6; i++) cpa16(dstb[i] + so, srcb[i] + (kt + 2) * 32);
        }
        CP_COMMIT();

        uint32_t st = sb + (kt % 3) * GST;
        uint32_t arow = st + (wm * 64 + (lane & 15)) * GROW + ((lane >> 4) << 4);
        uint32_t brow = st + 2 * GTILE +
                        (wn * 32 + (lane & 7) + ((lane >> 4) << 3)) * GROW +
                        (((lane >> 3) & 1) << 4);
#pragma unroll
        for (int kf = 0; kf < 2; kf++) {
            uint32_t ah[4][4], al[4][4];
#pragma unroll
            for (int mi = 0; mi < 4; mi++) {
                ldm4(ah[mi], arow + mi * 16 * GROW + kf * 32);
                ldm4(al[mi], arow + GTILE + mi * 16 * GROW + kf * 32);
            }
#pragma unroll
            for (int njp = 0; njp < 2; njp++) {
                uint32_t bh[4];
                ldm4(bh, brow + njp * 16 * GROW + kf * 32);
#pragma unroll
                for (int mi = 0; mi < 4; mi++) {
                    mma16816(acc[mi][2 * njp],     ah[mi], bh);
                    mma16816(acc[mi][2 * njp],     al[mi], bh);
                    mma16816(acc[mi][2 * njp + 1], ah[mi], bh + 2);
                    mma16816(acc[mi][2 * njp + 1], al[mi], bh + 2);
                }
            }
        }
        __syncthreads();
    }

#pragma unroll
    for (int mi = 0; mi < 4; mi++)
#pragma unroll
        for (int nj = 0; nj < 4; nj++) {
            size_t r0 = bm + wm * 64 + mi * 16 + (lane >> 2);
            size_t cc = bn + wn * 32 + nj * 8 + (lane & 3) * 2;
            *(float2*)&C[r0 * N + cc]       = make_float2(acc[mi][nj][0], acc[mi][nj][1]);
            *(float2*)&C[(r0 + 8) * N + cc] = make_float2(acc[mi][nj][2], acc[mi][nj][3]);
        }
}

// ---------------- HMMA fp16x2 flash attention, cp.async pipelined -------------
#define ATQ 272
#define S_QH 0
#define S_QL 17408
#define S_K  34816
#define S_V  52224
#define ATTN_SMEM 69632

__global__ __launch_bounds__(128) void attn_kernel(
    const __half* __restrict__ Qh, const __half* __restrict__ Ql,
    const __half* __restrict__ Kh, const __half* __restrict__ Vh,
    float* __restrict__ Y) {
    extern __shared__ __align__(128) char ash[];
    uint32_t sb = smem_u32(ash);
    int tid = threadIdx.x, lane = tid & 31, w = tid >> 5;
    int qb = blockIdx.x * 64, h = blockIdx.y, b = blockIdx.z;
    size_t tok0 = (size_t)b * TQn + qb;
    size_t ktok0 = (size_t)b * Tn;
    int hcol = h * 128;
    const float NI = neginf();
    const float scale = 0.08838834764831845f;

    // Q tile hi+lo (one-time)
#pragma unroll
    for (int i = 0; i < 16; i++) {
        int id = tid + i * 128;
        int buf = id >> 10, ww = id & 1023, row = ww >> 4, c = ww & 15;
        const __half* src = (buf ? Ql : Qh) + (tok0 + row) * HDn + hcol + c * 8;
        *(uint4*)(ash + (buf ? S_QL : S_QH) + row * ATQ + c * 16) = *(const uint4*)src;
    }
    __syncthreads();

    uint32_t qhf[8][4], qlf[8][4];
    {
        uint32_t abase = sb + (w * 16 + (lane & 15)) * ATQ + ((lane >> 4) << 4);
#pragma unroll
        for (int kf = 0; kf < 8; kf++) {
            ldm4(qhf[kf], abase + kf * 32);
            ldm4(qlf[kf], abase + S_QL + kf * 32);
        }
    }

    float oa[16][4];
#pragma unroll
    for (int i = 0; i < 16; i++)
#pragma unroll
        for (int j = 0; j < 4; j++) oa[i][j] = 0.f;
    float m_a = NI, m_b = NI, l_a = 0.f, l_b = 0.f;

    // cp.async tile issuers: 8 chunks/thread per 64x128 fp16 tile
    int crow = tid >> 4, ccol = tid & 15;
    uint32_t kdst = sb + S_K + crow * ATQ + ccol * 16;
    uint32_t vdst = sb + S_V + crow * ATQ + ccol * 16;
    const __half* ksrc0 = Kh + (ktok0 + crow) * HDn + hcol + ccol * 8;
    const __half* vsrc0 = Vh + (ktok0 + crow) * HDn + hcol + ccol * 8;

#define ISSUE_K(kt) do { \
    const __half* _s = ksrc0 + (size_t)(kt) * 64 * HDn; \
    _Pragma("unroll") for (int _i = 0; _i < 8; _i++) \
        cpa16(kdst + _i * 8 * ATQ, _s + (size_t)_i * 8 * HDn); \
} while (0)
#define ISSUE_V(kt) do { \
    const __half* _s = vsrc0 + (size_t)(kt) * 64 * HDn; \
    _Pragma("unroll") for (int _i = 0; _i < 8; _i++) \
        cpa16(vdst + _i * 8 * ATQ, _s + (size_t)_i * 8 * HDn); \
} while (0)

    ISSUE_K(0); CP_COMMIT();
    ISSUE_V(0); CP_COMMIT();

    for (int kt = 0; kt < Tn / 64; kt++) {
        // mask flags for this tile (L1-hot broadcast)
        const float* fb = &g_maskf[b * Tn + kt * 64 + (lane & 3) * 2];
        float f0[8], f1[8];
#pragma unroll
        for (int nf = 0; nf < 8; nf++) { f0[nf] = __ldg(fb + nf * 8); f1[nf] = __ldg(fb + nf * 8 + 1); }

        CP_WAIT1();          // K(kt) ready (V(kt) still pending)
        __syncthreads();

        // S = Q K^T
        float sc[8][4];
#pragma unroll
        for (int i = 0; i < 8; i++)
#pragma unroll
            for (int j = 0; j < 4; j++) sc[i][j] = 0.f;
        {
            uint32_t bbase = sb + S_K +
                ((lane & 7) + ((lane >> 4) << 3)) * ATQ + (((lane >> 3) & 1) << 4);
#pragma unroll
            for (int kf = 0; kf < 8; kf++) {
#pragma unroll
                for (int njp = 0; njp < 4; njp++) {
                    uint32_t kh4[4];
                    ldm4(kh4, bbase + njp * 16 * ATQ + kf * 32);
                    mma16816(sc[2 * njp],     qhf[kf], kh4);
                    mma16816(sc[2 * njp],     qlf[kf], kh4);
                    mma16816(sc[2 * njp + 1], qhf[kf], kh4 + 2);
                    mma16816(sc[2 * njp + 1], qlf[kf], kh4 + 2);
                }
            }
        }
        __syncthreads();     // all warps done reading K
        ISSUE_K((kt + 1) & 31); CP_COMMIT();   // overlaps softmax + PV

        // online softmax (rows in-warp, quad shfl)
        float ta = NI, tb = NI;
#pragma unroll
        for (int nf = 0; nf < 8; nf++) {
#pragma unroll
            for (int j = 0; j < 4; j++) sc[nf][j] *= scale;
            if (f0[nf] == 0.f) { ta = fmaxf(ta, sc[nf][0]); tb = fmaxf(tb, sc[nf][2]); }
            if (f1[nf] == 0.f) { ta = fmaxf(ta, sc[nf][1]); tb = fmaxf(tb, sc[nf][3]); }
        }
        ta = fmaxf(ta, __shfl_xor_sync(0xffffffffu, ta, 1));
        ta = fmaxf(ta, __shfl_xor_sync(0xffffffffu, ta, 2));
        tb = fmaxf(tb, __shfl_xor_sync(0xffffffffu, tb, 1));
        tb = fmaxf(tb, __shfl_xor_sync(0xffffffffu, tb, 2));
        float mna = fmaxf(m_a, ta), mnb = fmaxf(m_b, tb);
        float alpha_a = (m_a > NI) ? __expf(m_a - mna) : 1.f;
        float alpha_b = (m_b > NI) ? __expf(m_b - mnb) : 1.f;
        m_a = mna; m_b = mnb;

        float sa = 0.f, sbm = 0.f;
#pragma unroll
        for (int nf = 0; nf < 8; nf++) {
            float p0 = (f0[nf] != 0.f || m_a == NI) ? 0.f : __expf(sc[nf][0] - m_a);
            float p1 = (f1[nf] != 0.f || m_a == NI) ? 0.f : __expf(sc[nf][1] - m_a);
            float p2 = (f0[nf] != 0.f || m_b == NI) ? 0.f : __expf(sc[nf][2] - m_b);
            float p3 = (f1[nf] != 0.f || m_b == NI) ? 0.f : __expf(sc[nf][3] - m_b);
            sc[nf][0] = p0; sc[nf][1] = p1; sc[nf][2] = p2; sc[nf][3] = p3;
            sa += p0 + p1; sbm += p2 + p3;
        }
        sa  += __shfl_xor_sync(0xffffffffu, sa, 1);
        sa  += __shfl_xor_sync(0xffffffffu, sa, 2);
        sbm += __shfl_xor_sync(0xffffffffu, sbm, 1);
        sbm += __shfl_xor_sync(0xffffffffu, sbm, 2);
        l_a = l_a * alpha_a + sa;
        l_b = l_b * alpha_b + sbm;
#pragma unroll
        for (int nf = 0; nf < 16; nf++) {
            oa[nf][0] *= alpha_a; oa[nf][1] *= alpha_a;
            oa[nf][2] *= alpha_b; oa[nf][3] *= alpha_b;
        }

        // P fragments (fp16 hi/lo)
        uint32_t ph[4][4], pl[4][4];
#pragma unroll
        for (int t = 0; t < 4; t++) {
            split2h(sc[2 * t][0],     sc[2 * t][1],     ph[t][0], pl[t][0]);
            split2h(sc[2 * t][2],     sc[2 * t][3],     ph[t][1], pl[t][1]);
            split2h(sc[2 * t + 1][0], sc[2 * t + 1][1], ph[t][2], pl[t][2]);
            split2h(sc[2 * t + 1][2], sc[2 * t + 1][3], ph[t][3], pl[t][3]);
        }

        CP_WAIT1();          // V(kt) ready (K(kt+1) still pending)
        __syncthreads();

        // O += P V
        {
            uint32_t vbase = sb + S_V +
                ((lane & 7) + (((lane >> 3) & 1) << 3)) * ATQ + ((lane >> 4) << 4);
#pragma unroll
            for (int t = 0; t < 4; t++) {
#pragma unroll
                for (int njp = 0; njp < 8; njp++) {
                    uint32_t vh4[4];
                    ldm4t(vh4, vbase + t * 16 * ATQ + njp * 32);
                    int n0 = njp * 2, n1 = n0 + 1;
                    mma16816(oa[n0], ph[t], vh4);
                    mma16816(oa[n0], pl[t], vh4);
                    mma16816(oa[n1], ph[t], vh4 + 2);
                    mma16816(oa[n1], pl[t], vh4 + 2);
                }
            }
        }
        __syncthreads();     // all warps done reading V
        ISSUE_V((kt + 1) & 31); CP_COMMIT();   // overlaps next S
    }

    float ia = 1.f / l_a, ib = 1.f / l_b;
    size_t ra = (tok0 + w * 16 + (lane >> 2)) * HDn + hcol + (lane & 3) * 2;
#pragma unroll
    for (int nf = 0; nf < 16; nf++) {
        *(float2*)&Y[ra + nf * 8] = make_float2(oa[nf][0] * ia, oa[nf][1] * ia);
        *(float2*)&Y[ra + 8 * HDn + nf * 8] = make_float2(oa[nf][2] * ib, oa[nf][3] * ib);
    }
}

// ---------------- launch -----------------------------------------------------
extern "C" void kernel_launch(void* const* d_in, const int* in_sizes, int n_in,
                              void* d_out, int out_size) {
    const float* x       = (const float*)d_in[0];
    const float* xall    = (const float*)d_in[1];
    const int*   posx    = (const int*)d_in[2];
    const int*   posxall = (const int*)d_in[3];
    const void*  mask    = d_in[4];
    const float* Wq      = (const float*)d_in[5];
    const float* Wk      = (const float*)d_in[6];
    const float* Wv      = (const float*)d_in[7];
    const float* Wo      = (const float*)d_in[8];
    float* out = (float*)d_out;

    float *Qp, *Kp, *Vp, *Yp;
    cudaGetSymbolAddress((void**)&Qp, g_Q);
    cudaGetSymbolAddress((void**)&Kp, g_K);
    cudaGetSymbolAddress((void**)&Vp, g_V);
    cudaGetSymbolAddress((void**)&Yp, g_Y);
    __half *xh, *xl, *ah, *al, *qh, *ql, *kh, *vh, *yh, *yl, *wq, *wk, *wv, *wo;
    cudaGetSymbolAddress((void**)&xh, g_xh);
    cudaGetSymbolAddress((void**)&xl, g_xl);
    cudaGetSymbolAddress((void**)&ah, g_ah);
    cudaGetSymbolAddress((void**)&al, g_al);
    cudaGetSymbolAddress((void**)&qh, g_qh);
    cudaGetSymbolAddress((void**)&ql, g_ql);
    cudaGetSymbolAddress((void**)&kh, g_kh);
    cudaGetSymbolAddress((void**)&vh, g_vh);
    cudaGetSymbolAddress((void**)&yh, g_yh);
    cudaGetSymbolAddress((void**)&yl, g_yl);
    cudaGetSymbolAddress((void**)&wq, g_wq);
    cudaGetSymbolAddress((void**)&wk, g_wk);
    cudaGetSymbolAddress((void**)&wv, g_wv);
    cudaGetSymbolAddress((void**)&wo, g_wo);

    cudaFuncSetAttribute(bgemm_kernel, cudaFuncAttributeMaxDynamicSharedMemorySize, GSMEM);
    cudaFuncSetAttribute(attn_kernel, cudaFuncAttributeMaxDynamicSharedMemorySize, ATTN_SMEM);

    ropetab_kernel<<<(POSN * 64 + 255) / 256, 256>>>();
    sniff_kernel<<<1, 256>>>((const unsigned char*)mask);
    maskcvt_kernel<<<(Bb * Tn + 255) / 256, 256>>>(mask);

    const int NE4 = NTOK * En / 4;
    splitH2_kernel<<<(NE4 + 255) / 256, 256>>>(x,    xh, xl, NE4);
    splitH2_kernel<<<(NE4 + 255) / 256, 256>>>(xall, ah, al, NE4);
    dim3 gt(64, 64), bt(32, 8);
    splitT_kernel<<<gt, bt>>>(Wq, wq);
    splitT_kernel<<<gt, bt>>>(Wk, wk);
    splitT_kernel<<<gt, bt>>>(Wv, wv);
    splitT_kernel<<<gt, bt>>>(Wo, wo);

    dim3 gg(HDn / 128, NTOK / 128);
    bgemm_kernel<<<gg, 256, GSMEM>>>(xh, xl, wq, Qp, NTOK, HDn, En);
    bgemm_kernel<<<gg, 256, GSMEM>>>(ah, al, wk, Kp, NTOK, HDn, En);
    bgemm_kernel<<<gg, 256, GSMEM>>>(ah, al, wv, Vp, NTOK, HDn, En);

    rope_splitH_kernel<<<(NTOK * Hn * 64 + 255) / 256, 256>>>(Qp, posx, qh, ql);
    rope_singleH_kernel<<<(NTOK * Hn * 64 + 255) / 256, 256>>>(Kp, posxall, kh);
    cvtH_kernel<<<(NE4 + 255) / 256, 256>>>(Vp, vh, NE4);

    dim3 ga(TQn / 64, Hn, Bb);
    attn_kernel<<<ga, 128, ATTN_SMEM>>>(qh, ql, kh, vh, Yp);

    splitH2_kernel<<<(NE4 + 255) / 256, 256>>>(Yp, yh, yl, NE4);
    bgemm_kernel<<<gg, 256, GSMEM>>>(yh, yl, wo, out, NTOK, En, HDn);
}

// round 9
// speedup vs baseline: 7.5886x; 1.0731x over previous
#include <cuda_runtime.h>
#include <cuda_fp16.h>
#include <cuda_bf16.h>
#include <math.h>
#include <stdint.h>

#define Bb 4
#define TQn 2048
#define Tn 2048
#define En 2048
#define Hn 16
#define Dn 128
#define HDn 2048
#define NTOK 8192
#define POSN 4096

// ---------------- scratch ----------------------------------------------------
__device__ float g_cos[POSN * 64];
__device__ float g_sin[POSN * 64];
__device__ int   g_kind;
__device__ int   g_sel[NTOK];     // per-batch compacted source token indices
__device__ int   g_nkeep[Bb];

__device__ __half g_xh[(size_t)NTOK * En];
__device__ __half g_xl[(size_t)NTOK * En];
__device__ __half g_ah[(size_t)NTOK * En];
__device__ __half g_al[(size_t)NTOK * En];
__device__ __half g_qh[(size_t)NTOK * HDn];
__device__ __half g_ql[(size_t)NTOK * HDn];
__device__ __half g_kh[(size_t)NTOK * HDn];
__device__ __half g_vh[(size_t)NTOK * HDn];
__device__ __half g_yh[(size_t)NTOK * HDn];
__device__ __half g_yl[(size_t)NTOK * HDn];
__device__ __half g_wq[(size_t)En * HDn];
__device__ __half g_wk[(size_t)En * HDn];
__device__ __half g_wv[(size_t)En * HDn];
__device__ __half g_wo[(size_t)En * HDn];

// ---------------- helpers ----------------------------------------------------
__device__ __forceinline__ float neginf() { return __int_as_float(0xff800000u); }

__device__ __forceinline__ uint32_t smem_u32(const void* p) {
    uint32_t a;
    asm("{ .reg .u64 t; cvta.to.shared.u64 t, %1; cvt.u32.u64 %0, t; }" : "=r"(a) : "l"(p));
    return a;
}
__device__ __forceinline__ void mma16816(float* d, const uint32_t* a, const uint32_t* b) {
    asm volatile("mma.sync.aligned.m16n8k16.row.col.f32.f16.f16.f32 "
        "{%0,%1,%2,%3}, {%4,%5,%6,%7}, {%8,%9}, {%0,%1,%2,%3};"
        : "+f"(d[0]), "+f"(d[1]), "+f"(d[2]), "+f"(d[3])
        : "r"(a[0]), "r"(a[1]), "r"(a[2]), "r"(a[3]), "r"(b[0]), "r"(b[1]));
}
__device__ __forceinline__ void ldm4(uint32_t* r, uint32_t a) {
    asm volatile("ldmatrix.sync.aligned.m8n8.x4.shared.b16 {%0,%1,%2,%3}, [%4];"
        : "=r"(r[0]), "=r"(r[1]), "=r"(r[2]), "=r"(r[3]) : "r"(a));
}
__device__ __forceinline__ void ldm4t(uint32_t* r, uint32_t a) {
    asm volatile("ldmatrix.sync.aligned.m8n8.x4.trans.shared.b16 {%0,%1,%2,%3}, [%4];"
        : "=r"(r[0]), "=r"(r[1]), "=r"(r[2]), "=r"(r[3]) : "r"(a));
}
__device__ __forceinline__ void cpa16(uint32_t d, const void* s) {
    asm volatile("cp.async.cg.shared.global [%0], [%1], 16;" :: "r"(d), "l"(s));
}
#define CP_COMMIT() asm volatile("cp.async.commit_group;" ::: "memory")
#define CP_WAIT1()  asm volatile("cp.async.wait_group 1;" ::: "memory")

__device__ __forceinline__ void split2h(float a, float b, uint32_t& hi, uint32_t& lo) {
    __half2 h = __floats2half2_rn(a, b);
    hi = *(uint32_t*)&h;
    __half2 l = __floats2half2_rn(a - __low2float(h), b - __high2float(h));
    lo = *(uint32_t*)&l;
}

__device__ __forceinline__ bool mask_at(const void* m, int i, int k) {
    if (k == 0) return ((const unsigned char*)m)[i] != 0;
    if (k == 1) return ((const int*)m)[i] != 0;
    if (k == 2) return ((const float*)m)[i] != 0.0f;
    return __bfloat162float(((const __nv_bfloat16*)m)[i]) != 0.0f;
}

// ---------------- small kernels ---------------------------------------------
__global__ void ropetab_kernel() {
    int t = blockIdx.x * 256 + threadIdx.x;
    if (t >= POSN * 64) return;
    int j = t & 63, p = t >> 6;
    double inv = 1.0 / pow(10000.0, (double)(2 * j) / 128.0);
    float invf = (float)inv;
    float ang = (float)p * invf;
    g_cos[t] = (float)cos((double)ang);
    g_sin[t] = (float)sin((double)ang);
}

__global__ void sniff_kernel(const unsigned char* m) {
    __shared__ int f[3];
    if (threadIdx.x < 3) f[threadIdx.x] = 0;
    __syncthreads();
    int a = 0, b = 0, c = 0;
    for (int i = threadIdx.x; i < Bb * Tn; i += 256) {
        unsigned v = m[i];
        if (v > 1) a = 1;
        if (v != 0 && (i & 3)) b = 1;
        if (v != 0 && ((i & 3) < 2)) c = 1;
    }
    if (a) atomicOr(&f[0], 1);
    if (b) atomicOr(&f[1], 1);
    if (c) atomicOr(&f[2], 1);
    __syncthreads();
    if (threadIdx.x == 0)
        g_kind = (!f[0]) ? (f[1] ? 0 : 1) : (f[2] ? 3 : 2);
}

// per-batch compaction: sel (unmasked token indices, tail filled safe), nkeep
__global__ void selbuild_kernel(const void* m) {
    __shared__ int sc[1024];
    __shared__ int stot;
    int b = blockIdx.x, tid = threadIdx.x;
    int kind = g_kind;
    int i0 = tid * 2, i1 = i0 + 1;
    int k0 = mask_at(m, b * Tn + i0, kind) ? 0 : 1;
    int k1 = mask_at(m, b * Tn + i1, kind) ? 0 : 1;
    int part = k0 + k1;
    sc[tid] = part;
    __syncthreads();
    for (int off = 1; off < 1024; off <<= 1) {
        int v = (tid >= off) ? sc[tid - off] : 0;
        __syncthreads();
        sc[tid] += v;
        __syncthreads();
    }
    int base = sc[tid] - part;
    if (k0) g_sel[b * Tn + base] = b * Tn + i0;
    if (k1) g_sel[b * Tn + base + k0] = b * Tn + i1;
    if (tid == 1023) { g_nkeep[b] = sc[1023]; stot = sc[1023]; }
    __syncthreads();
    for (int i = stot + tid; i < Tn; i += 1024) g_sel[b * Tn + i] = b * Tn;
}

// fp32 -> fp16 hi/lo split
__global__ void splitH2_kernel(const float* __restrict__ in,
                               __half* __restrict__ hi, __half* __restrict__ lo,
                               int n4) {
    int i = blockIdx.x * 256 + threadIdx.x;
    if (i >= n4) return;
    float4 v = ((const float4*)in)[i];
    uint32_t h0, l0, h1, l1;
    split2h(v.x, v.y, h0, l0);
    split2h(v.z, v.w, h1, l1);
    ((uint32_t*)hi)[i * 2]     = h0;
    ((uint32_t*)hi)[i * 2 + 1] = h1;
    ((uint32_t*)lo)[i * 2]     = l0;
    ((uint32_t*)lo)[i * 2 + 1] = l1;
}

// W[K][N] -> Wt[N][K] fp16, optional rope column permutation of N
__global__ void splitT_kernel(const float* __restrict__ W, __half* __restrict__ out,
                              int perm) {
    __shared__ float t[32][33];
    int n0 = blockIdx.x * 32, k0 = blockIdx.y * 32;
    for (int r = threadIdx.y; r < 32; r += 8)
        t[r][threadIdx.x] = W[(size_t)(k0 + r) * 2048 + n0 + threadIdx.x];
    __syncthreads();
    for (int r = threadIdx.y; r < 32; r += 8) {
        int n = n0 + r;
        int rr = n & 127;
        int nout = perm ? ((n & ~127) | (rr < 64 ? (rr * 2) : ((rr - 64) * 2 + 1))) : n;
        out[(size_t)nout * 2048 + k0 + threadIdx.x] = __float2half(t[threadIdx.x][r]);
    }
}

// ---------------- HMMA fp16x2 GEMM with fused epilogues ----------------------
// MODE 0: fp32 C.  MODE 1: rope + hi/lo half (Q).  MODE 2: rope + single half (K).
// MODE 3: single half (V).  Asel: A-row indirection (compaction). nkp: early exit.
#define GROW 80
#define GTILE 10240
#define GST  30720
#define GSMEM (3 * GST)

template<int MODE>
__global__ __launch_bounds__(256, 1) void bgemm_kernel(
    const __half* __restrict__ Ahi, const __half* __restrict__ Alo,
    const __half* __restrict__ Bh, float* __restrict__ Cf,
    __half* __restrict__ Oh, __half* __restrict__ Ol,
    const int* __restrict__ Asel, const int* __restrict__ pos,
    const int* __restrict__ nkp, int M, int N, int K) {
    extern __shared__ __align__(128) char gsm[];
    uint32_t sb = smem_u32(gsm);
    int tid = threadIdx.x, lane = tid & 31, wid = tid >> 5;
    int wm = wid & 1, wn = wid >> 1;
    size_t bm = (size_t)blockIdx.y * 128, bn = (size_t)blockIdx.x * 128;

    if (nkp != nullptr) {
        if ((int)(bm & (Tn - 1)) >= nkp[bm >> 11]) return;   // whole block dead
    }

    const __half* srcb[6];
    uint32_t dstb[6];
#pragma unroll
    for (int i = 0; i < 6; i++) {
        int id = tid + i * 256, tile = id >> 9, w = id & 511, row = w >> 2, c = w & 3;
        const __half* base = (tile == 0) ? Ahi : (tile == 1) ? Alo : Bh;
        size_t grow;
        if (tile < 2) grow = Asel ? (size_t)Asel[bm + row] : (bm + row);
        else          grow = bn + row;
        srcb[i] = base + grow * (size_t)K + c * 8;
        dstb[i] = sb + tile * GTILE + row * GROW + c * 16;
    }

    float acc[4][4][4];
#pragma unroll
    for (int a = 0; a < 4; a++)
#pragma unroll
        for (int b = 0; b < 4; b++)
#pragma unroll
            for (int c = 0; c < 4; c++) acc[a][b][c] = 0.f;

    const int NT = K / 32;
#pragma unroll
    for (int s = 0; s < 2; s++) {
#pragma unroll
        for (int i = 0; i < 6; i++) cpa16(dstb[i] + s * GST, srcb[i] + s * 32);
        CP_COMMIT();
    }

    for (int kt = 0; kt < NT; kt++) {
        CP_WAIT1();
        __syncthreads();
        if (kt + 2 < NT) {
            uint32_t so = ((kt + 2) % 3) * GST;
#pragma unroll
            for (int i = 0; i < 6; i++) cpa16(dstb[i] + so, srcb[i] + (kt + 2) * 32);
        }
        CP_COMMIT();

        uint32_t st = sb + (kt % 3) * GST;
        uint32_t arow = st + (wm * 64 + (lane & 15)) * GROW + ((lane >> 4) << 4);
        uint32_t brow = st + 2 * GTILE +
                        (wn * 32 + (lane & 7) + ((lane >> 4) << 3)) * GROW +
                        (((lane >> 3) & 1) << 4);
#pragma unroll
        for (int kf = 0; kf < 2; kf++) {
            uint32_t ah[4][4], al[4][4];
#pragma unroll
            for (int mi = 0; mi < 4; mi++) {
                ldm4(ah[mi], arow + mi * 16 * GROW + kf * 32);
                ldm4(al[mi], arow + GTILE + mi * 16 * GROW + kf * 32);
            }
#pragma unroll
            for (int njp = 0; njp < 2; njp++) {
                uint32_t bh[4];
                ldm4(bh, brow + njp * 16 * GROW + kf * 32);
#pragma unroll
                for (int mi = 0; mi < 4; mi++) {
                    mma16816(acc[mi][2 * njp],     ah[mi], bh);
                    mma16816(acc[mi][2 * njp],     al[mi], bh);
                    mma16816(acc[mi][2 * njp + 1], ah[mi], bh + 2);
                    mma16816(acc[mi][2 * njp + 1], al[mi], bh + 2);
                }
            }
        }
        __syncthreads();
    }

    // epilogue
#pragma unroll
    for (int mi = 0; mi < 4; mi++) {
        size_t r0 = bm + wm * 64 + mi * 16 + (lane >> 2);
        size_t r1 = r0 + 8;
        int p0 = 0, p1 = 0;
        if (MODE == 1 || MODE == 2) {
            p0 = pos[Asel ? Asel[r0] : (int)r0];
            p1 = pos[Asel ? Asel[r1] : (int)r1];
        }
#pragma unroll
        for (int nj = 0; nj < 4; nj++) {
            size_t cc = bn + wn * 32 + nj * 8 + (lane & 3) * 2;
            float a0 = acc[mi][nj][0], b0 = acc[mi][nj][1];
            float a1 = acc[mi][nj][2], b1 = acc[mi][nj][3];
            if (MODE == 0) {
                *(float2*)&Cf[r0 * N + cc] = make_float2(a0, b0);
                *(float2*)&Cf[r1 * N + cc] = make_float2(a1, b1);
            } else if (MODE == 3) {
                *(__half2*)&Oh[r0 * N + cc] = __floats2half2_rn(a0, b0);
                *(__half2*)&Oh[r1 * N + cc] = __floats2half2_rn(a1, b1);
            } else {
                int j = ((int)cc & 127) >> 1;
                float c0 = g_cos[p0 * 64 + j], s0 = g_sin[p0 * 64 + j];
                float c1 = g_cos[p1 * 64 + j], s1 = g_sin[p1 * 64 + j];
                float e0 = a0 * c0 - b0 * s0, o0 = b0 * c0 + a0 * s0;
                float e1 = a1 * c1 - b1 * s1, o1 = b1 * c1 + a1 * s1;
                if (MODE == 1) {
                    uint32_t h, l;
                    split2h(e0, o0, h, l);
                    *(uint32_t*)&Oh[r0 * N + cc] = h;
                    *(uint32_t*)&Ol[r0 * N + cc] = l;
                    split2h(e1, o1, h, l);
                    *(uint32_t*)&Oh[r1 * N + cc] = h;
                    *(uint32_t*)&Ol[r1 * N + cc] = l;
                } else {
                    *(__half2*)&Oh[r0 * N + cc] = __floats2half2_rn(e0, o0);
                    *(__half2*)&Oh[r1 * N + cc] = __floats2half2_rn(e1, o1);
                }
            }
        }
    }
}

// ---------------- HMMA fp16x2 flash attention (compacted keys) ---------------
#define ATQ 272
#define S_QH 0
#define S_QL 17408
#define S_K  34816
#define S_V  52224
#define ATTN_SMEM 69632

__global__ __launch_bounds__(128) void attn_kernel(
    const __half* __restrict__ Qh, const __half* __restrict__ Ql,
    const __half* __restrict__ Kh, const __half* __restrict__ Vh,
    __half* __restrict__ Yh, __half* __restrict__ Yl) {
    extern __shared__ __align__(128) char ash[];
    uint32_t sb = smem_u32(ash);
    int tid = threadIdx.x, lane = tid & 31, w = tid >> 5;
    int qb = blockIdx.x * 64, h = blockIdx.y, b = blockIdx.z;
    size_t tok0 = (size_t)b * TQn + qb;
    size_t ktok0 = (size_t)b * Tn;
    int hcol = h * 128;
    const float NI = neginf();
    const float scale = 0.08838834764831845f;
    const int nk = g_nkeep[b];
    const int nt = (nk + 63) >> 6;

#pragma unroll
    for (int i = 0; i < 16; i++) {
        int id = tid + i * 128;
        int buf = id >> 10, ww = id & 1023, row = ww >> 4, c = ww & 15;
        const __half* src = (buf ? Ql : Qh) + (tok0 + row) * HDn + hcol + c * 8;
        *(uint4*)(ash + (buf ? S_QL : S_QH) + row * ATQ + c * 16) = *(const uint4*)src;
    }
    __syncthreads();

    uint32_t qhf[8][4], qlf[8][4];
    {
        uint32_t abase = sb + (w * 16 + (lane & 15)) * ATQ + ((lane >> 4) << 4);
#pragma unroll
        for (int kf = 0; kf < 8; kf++) {
            ldm4(qhf[kf], abase + kf * 32);
            ldm4(qlf[kf], abase + S_QL + kf * 32);
        }
    }

    float oa[16][4];
#pragma unroll
    for (int i = 0; i < 16; i++)
#pragma unroll
        for (int j = 0; j < 4; j++) oa[i][j] = 0.f;
    float m_a = NI, m_b = NI, l_a = 0.f, l_b = 0.f;

    int crow = tid >> 4, ccol = tid & 15;
    uint32_t kdst = sb + S_K + crow * ATQ + ccol * 16;
    uint32_t vdst = sb + S_V + crow * ATQ + ccol * 16;
    const __half* ksrc0 = Kh + (ktok0 + crow) * HDn + hcol + ccol * 8;
    const __half* vsrc0 = Vh + (ktok0 + crow) * HDn + hcol + ccol * 8;

#define ISSUE_K(kt) do { \
    const __half* _s = ksrc0 + (size_t)(kt) * 64 * HDn; \
    _Pragma("unroll") for (int _i = 0; _i < 8; _i++) \
        cpa16(kdst + _i * 8 * ATQ, _s + (size_t)_i * 8 * HDn); \
} while (0)
#define ISSUE_V(kt) do { \
    const __half* _s = vsrc0 + (size_t)(kt) * 64 * HDn; \
    _Pragma("unroll") for (int _i = 0; _i < 8; _i++) \
        cpa16(vdst + _i * 8 * ATQ, _s + (size_t)_i * 8 * HDn); \
} while (0)

    ISSUE_K(0); CP_COMMIT();
    ISSUE_V(0); CP_COMMIT();

    for (int kt = 0; kt < nt; kt++) {
        CP_WAIT1();
        __syncthreads();

        // S = Q K^T
        float sc[8][4];
#pragma unroll
        for (int i = 0; i < 8; i++)
#pragma unroll
            for (int j = 0; j < 4; j++) sc[i][j] = 0.f;
        {
            uint32_t bbase = sb + S_K +
                ((lane & 7) + ((lane >> 4) << 3)) * ATQ + (((lane >> 3) & 1) << 4);
#pragma unroll
            for (int kf = 0; kf < 8; kf++) {
#pragma unroll
                for (int njp = 0; njp < 4; njp++) {
                    uint32_t kh4[4];
                    ldm4(kh4, bbase + njp * 16 * ATQ + kf * 32);
                    mma16816(sc[2 * njp],     qhf[kf], kh4);
                    mma16816(sc[2 * njp],     qlf[kf], kh4);
                    mma16816(sc[2 * njp + 1], qhf[kf], kh4 + 2);
                    mma16816(sc[2 * njp + 1], qlf[kf], kh4 + 2);
                }
            }
        }
        __syncthreads();
        ISSUE_K((kt + 1) & 31); CP_COMMIT();

        // validity from compaction (register compare, no loads)
        float ta = NI, tb = NI;
        bool v0[8], v1[8];
#pragma unroll
        for (int nf = 0; nf < 8; nf++) {
            int key0 = kt * 64 + nf * 8 + ((lane & 3) << 1);
            v0[nf] = key0 < nk;
            v1[nf] = key0 + 1 < nk;
#pragma unroll
            for (int j = 0; j < 4; j++) sc[nf][j] *= scale;
            if (v0[nf]) { ta = fmaxf(ta, sc[nf][0]); tb = fmaxf(tb, sc[nf][2]); }
            if (v1[nf]) { ta = fmaxf(ta, sc[nf][1]); tb = fmaxf(tb, sc[nf][3]); }
        }
        ta = fmaxf(ta, __shfl_xor_sync(0xffffffffu, ta, 1));
        ta = fmaxf(ta, __shfl_xor_sync(0xffffffffu, ta, 2));
        tb = fmaxf(tb, __shfl_xor_sync(0xffffffffu, tb, 1));
        tb = fmaxf(tb, __shfl_xor_sync(0xffffffffu, tb, 2));
        float mna = fmaxf(m_a, ta), mnb = fmaxf(m_b, tb);
        float alpha_a = (m_a > NI) ? __expf(m_a - mna) : 1.f;
        float alpha_b = (m_b > NI) ? __expf(m_b - mnb) : 1.f;
        m_a = mna; m_b = mnb;

        float sa = 0.f, sbm = 0.f;
#pragma unroll
        for (int nf = 0; nf < 8; nf++) {
            float p0 = (!v0[nf] || m_a == NI) ? 0.f : __expf(sc[nf][0] - m_a);
            float p1 = (!v1[nf] || m_a == NI) ? 0.f : __expf(sc[nf][1] - m_a);
            float p2 = (!v0[nf] || m_b == NI) ? 0.f : __expf(sc[nf][2] - m_b);
            float p3 = (!v1[nf] || m_b == NI) ? 0.f : __expf(sc[nf][3] - m_b);
            sc[nf][0] = p0; sc[nf][1] = p1; sc[nf][2] = p2; sc[nf][3] = p3;
            sa += p0 + p1; sbm += p2 + p3;
        }
        sa  += __shfl_xor_sync(0xffffffffu, sa, 1);
        sa  += __shfl_xor_sync(0xffffffffu, sa, 2);
        sbm += __shfl_xor_sync(0xffffffffu, sbm, 1);
        sbm += __shfl_xor_sync(0xffffffffu, sbm, 2);
        l_a = l_a * alpha_a + sa;
        l_b = l_b * alpha_b + sbm;
#pragma unroll
        for (int nf = 0; nf < 16; nf++) {
            oa[nf][0] *= alpha_a; oa[nf][1] *= alpha_a;
            oa[nf][2] *= alpha_b; oa[nf][3] *= alpha_b;
        }

        uint32_t ph[4][4], pl[4][4];
#pragma unroll
        for (int t = 0; t < 4; t++) {
            split2h(sc[2 * t][0],     sc[2 * t][1],     ph[t][0], pl[t][0]);
            split2h(sc[2 * t][2],     sc[2 * t][3],     ph[t][1], pl[t][1]);
            split2h(sc[2 * t + 1][0], sc[2 * t + 1][1], ph[t][2], pl[t][2]);
            split2h(sc[2 * t + 1][2], sc[2 * t + 1][3], ph[t][3], pl[t][3]);
        }

        CP_WAIT1();
        __syncthreads();

        // O += P V
        {
            uint32_t vbase = sb + S_V +
                ((lane & 7) + (((lane >> 3) & 1) << 3)) * ATQ + ((lane >> 4) << 4);
#pragma unroll
            for (int t = 0; t < 4; t++) {
#pragma unroll
                for (int njp = 0; njp < 8; njp++) {
                    uint32_t vh4[4];
                    ldm4t(vh4, vbase + t * 16 * ATQ + njp * 32);
                    int n0 = njp * 2, n1 = n0 + 1;
                    mma16816(oa[n0], ph[t], vh4);
                    mma16816(oa[n0], pl[t], vh4);
                    mma16816(oa[n1], ph[t], vh4 + 2);
                    mma16816(oa[n1], pl[t], vh4 + 2);
                }
            }
        }
        __syncthreads();
        ISSUE_V((kt + 1) & 31); CP_COMMIT();
    }

    float ia = 1.f / l_a, ib = 1.f / l_b;
    size_t ra = (tok0 + w * 16 + (lane >> 2)) * HDn + hcol + (lane & 3) * 2;
#pragma unroll
    for (int nf = 0; nf < 16; nf++) {
        uint32_t h, l;
        split2h(oa[nf][0] * ia, oa[nf][1] * ia, h, l);
        *(uint32_t*)&Yh[ra + nf * 8] = h;
        *(uint32_t*)&Yl[ra + nf * 8] = l;
        split2h(oa[nf][2] * ib, oa[nf][3] * ib, h, l);
        *(uint32_t*)&Yh[ra + 8 * HDn + nf * 8] = h;
        *(uint32_t*)&Yl[ra + 8 * HDn + nf * 8] = l;
    }
}

// ---------------- launch -----------------------------------------------------
extern "C" void kernel_launch(void* const* d_in, const int* in_sizes, int n_in,
                              void* d_out, int out_size) {
    const float* x       = (const float*)d_in[0];
    const float* xall    = (const float*)d_in[1];
    const int*   posx    = (const int*)d_in[2];
    const int*   posxall = (const int*)d_in[3];
    const void*  mask    = d_in[4];
    const float* Wq      = (const float*)d_in[5];
    const float* Wk      = (const float*)d_in[6];
    const float* Wv      = (const float*)d_in[7];
    const float* Wo      = (const float*)d_in[8];
    float* out = (float*)d_out;

    __half *xh, *xl, *ah, *al, *qh, *ql, *kh, *vh, *yh, *yl, *wq, *wk, *wv, *wo;
    int *sel, *nkp;
    cudaGetSymbolAddress((void**)&xh, g_xh);
    cudaGetSymbolAddress((void**)&xl, g_xl);
    cudaGetSymbolAddress((void**)&ah, g_ah);
    cudaGetSymbolAddress((void**)&al, g_al);
    cudaGetSymbolAddress((void**)&qh, g_qh);
    cudaGetSymbolAddress((void**)&ql, g_ql);
    cudaGetSymbolAddress((void**)&kh, g_kh);
    cudaGetSymbolAddress((void**)&vh, g_vh);
    cudaGetSymbolAddress((void**)&yh, g_yh);
    cudaGetSymbolAddress((void**)&yl, g_yl);
    cudaGetSymbolAddress((void**)&wq, g_wq);
    cudaGetSymbolAddress((void**)&wk, g_wk);
    cudaGetSymbolAddress((void**)&wv, g_wv);
    cudaGetSymbolAddress((void**)&wo, g_wo);
    cudaGetSymbolAddress((void**)&sel, g_sel);
    cudaGetSymbolAddress((void**)&nkp, g_nkeep);

    cudaFuncSetAttribute(bgemm_kernel<0>, cudaFuncAttributeMaxDynamicSharedMemorySize, GSMEM);
    cudaFuncSetAttribute(bgemm_kernel<1>, cudaFuncAttributeMaxDynamicSharedMemorySize, GSMEM);
    cudaFuncSetAttribute(bgemm_kernel<2>, cudaFuncAttributeMaxDynamicSharedMemorySize, GSMEM);
    cudaFuncSetAttribute(bgemm_kernel<3>, cudaFuncAttributeMaxDynamicSharedMemorySize, GSMEM);
    cudaFuncSetAttribute(attn_kernel, cudaFuncAttributeMaxDynamicSharedMemorySize, ATTN_SMEM);

    ropetab_kernel<<<(POSN * 64 + 255) / 256, 256>>>();
    sniff_kernel<<<1, 256>>>((const unsigned char*)mask);
    selbuild_kernel<<<Bb, 1024>>>(mask);

    const int NE4 = NTOK * En / 4;
    splitH2_kernel<<<(NE4 + 255) / 256, 256>>>(x,    xh, xl, NE4);
    splitH2_kernel<<<(NE4 + 255) / 256, 256>>>(xall, ah, al, NE4);
    dim3 gt(64, 64), bt(32, 8);
    splitT_kernel<<<gt, bt>>>(Wq, wq, 1);
    splitT_kernel<<<gt, bt>>>(Wk, wk, 1);
    splitT_kernel<<<gt, bt>>>(Wv, wv, 0);
    splitT_kernel<<<gt, bt>>>(Wo, wo, 0);

    dim3 gg(HDn / 128, NTOK / 128);
    // Q: rope + hi/lo, full rows
    bgemm_kernel<1><<<gg, 256, GSMEM>>>(xh, xl, wq, nullptr, qh, ql,
                                        nullptr, posx, nullptr, NTOK, HDn, En);
    // K: rope + single, compacted rows
    bgemm_kernel<2><<<gg, 256, GSMEM>>>(ah, al, wk, nullptr, kh, nullptr,
                                        sel, posxall, nkp, NTOK, HDn, En);
    // V: single, compacted rows
    bgemm_kernel<3><<<gg, 256, GSMEM>>>(ah, al, wv, nullptr, vh, nullptr,
                                        sel, nullptr, nkp, NTOK, HDn, En);

    dim3 ga(TQn / 64, Hn, Bb);
    attn_kernel<<<ga, 128, ATTN_SMEM>>>(qh, ql, kh, vh, yh, yl);

    // out projection: fp32 C
    dim3 go(En / 128, NTOK / 128);
    bgemm_kernel<0><<<go, 256, GSMEM>>>(yh, yl, wo, out, nullptr, nullptr,
                                        nullptr, nullptr, nullptr, NTOK, En, HDn);
}